// round 15
// baseline (speedup 1.0000x reference)
#include <cuda_runtime.h>
#include <cuda_bf16.h>
#include <math.h>
#include <stdint.h>

#define NN 50000
#define EE 800000
#define HH 128
#define NC 40

// ==================== scratch ====================
__device__ int   g_is64;
__device__ int   g_cnt[NN];
__device__ int   g_part[256];
__device__ int   g_rowptr[NN + 1];
__device__ int   g_wr[NN];
__device__ int   g_col[EE];
__device__ float g_dis[NN];
__device__ float g_sn[NN];
__device__ float g_ls[NN], g_ld[NN];
__device__ float g_vs[3 * HH], g_vd[3 * HH];
__device__ float g_h0[NN * HH];
__device__ float g_x1[NN * HH], g_x2[NN * HH], g_x3[NN * HH];
__device__ float g_gcnin[NN * HH], g_gatin[NN * HH];
__device__ float g_aggn[NN * HH], g_ginin[NN * HH];
__device__ float g_naw[12], g_scw[4], g_law[3];
__device__ __nv_bfloat16 g_wh[16 * 16384];
__device__ __nv_bfloat16 g_wl[16 * 16384];

template <int ID>
__device__ __forceinline__ float* buf() {
    if (ID == 0)  return g_h0;
    if (ID == 1)  return g_x1;
    if (ID == 2)  return g_x2;
    if (ID == 3)  return g_x3;
    if (ID == 4)  return g_gcnin;
    if (ID == 5)  return g_gatin;
    if (ID == 6)  return g_aggn;
    return g_ginin;
}

__device__ __forceinline__ float eluf(float x) { return x > 0.f ? x : __expf(x) - 1.f; }
__device__ __forceinline__ int edge_at(const void* p, int idx) {
    if (g_is64) return (int)((const long long*)p)[idx];
    return ((const int*)p)[idx];
}
__device__ __forceinline__ uint32_t smem_u32(const void* p) {
    uint32_t a;
    asm("{ .reg .u64 t; cvta.to.shared.u64 t, %1; cvt.u32.u64 %0, t; }" : "=r"(a) : "l"(p));
    return a;
}
__device__ __forceinline__ unsigned pack2bf(__nv_bfloat16 a, __nv_bfloat16 b) {
    return (unsigned)__bfloat16_as_ushort(a) | ((unsigned)__bfloat16_as_ushort(b) << 16);
}

// ==================== edge dtype detection ====================
__global__ void detect_kernel(const int* __restrict__ p) {
    __shared__ int nz;
    if (threadIdx.x == 0) nz = 0;
    __syncthreads();
    int local = 0;
    for (int i = threadIdx.x * 2 + 1; i < 8192; i += 2 * blockDim.x)
        if (p[i] != 0) local = 1;
    if (local) atomicOr(&nz, 1);
    __syncthreads();
    if (threadIdx.x == 0) g_is64 = nz ? 0 : 1;
}

// ==================== tiny softmaxes ====================
__global__ void softmax_small_kernel(const float* __restrict__ na,
                                     const float* __restrict__ sc,
                                     const float* __restrict__ la) {
    if (threadIdx.x != 0 || blockIdx.x != 0) return;
    for (int r = 0; r < 3; r++) {
        float m = -1e30f;
        for (int j = 0; j < 4; j++) m = fmaxf(m, na[r * 4 + j]);
        float z = 0.f, e[4];
        for (int j = 0; j < 4; j++) { e[j] = expf(na[r * 4 + j] - m); z += e[j]; }
        for (int j = 0; j < 4; j++) g_naw[r * 4 + j] = e[j] / z;
    }
    for (int r = 0; r < 2; r++) {
        float m = fmaxf(sc[r * 2], sc[r * 2 + 1]);
        float e0 = expf(sc[r * 2] - m), e1 = expf(sc[r * 2 + 1] - m);
        g_scw[r * 2] = e0 / (e0 + e1);
        g_scw[r * 2 + 1] = e1 / (e0 + e1);
    }
    {
        float m = fmaxf(fmaxf(la[0], la[1]), la[2]);
        float e0 = expf(la[0] - m), e1 = expf(la[1] - m), e2 = expf(la[2] - m);
        float z = e0 + e1 + e2;
        g_law[0] = e0 / z; g_law[1] = e1 / z; g_law[2] = e2 / z;
    }
}

// ==================== CSR build ====================
__global__ void zero_cnt_kernel() {
    int i = blockIdx.x * blockDim.x + threadIdx.x;
    if (i < NN) g_cnt[i] = 0;
}
__global__ void count_kernel(const void* __restrict__ ei) {
    int e = blockIdx.x * blockDim.x + threadIdx.x;
    if (e >= EE) return;
    int dst = edge_at(ei, EE + e);
    if ((unsigned)dst >= NN) return;
    atomicAdd(&g_cnt[dst], 1);
}
__global__ void scan_part() {
    int tid = threadIdx.x, lane = tid & 31, wid = tid >> 5;
    int idx = blockIdx.x * 256 + tid;
    int v = (idx < NN) ? g_cnt[idx] : 0;
#pragma unroll
    for (int off = 16; off; off >>= 1) v += __shfl_xor_sync(0xffffffffu, v, off);
    __shared__ int ws[8];
    if (lane == 0) ws[wid] = v;
    __syncthreads();
    if (tid == 0) {
        int s = 0;
#pragma unroll
        for (int i = 0; i < 8; i++) s += ws[i];
        g_part[blockIdx.x] = s;
    }
}
__global__ void scan_mid() {
    int tid = threadIdx.x, lane = tid & 31, wid = tid >> 5;
    int v = (tid < 196) ? g_part[tid] : 0;
    int incl = v;
#pragma unroll
    for (int off = 1; off < 32; off <<= 1) {
        int t = __shfl_up_sync(0xffffffffu, incl, off);
        if (lane >= off) incl += t;
    }
    __shared__ int ws[8];
    __shared__ int tot;
    if (lane == 31) ws[wid] = incl;
    __syncthreads();
    if (wid == 0) {
        int u = (lane < 8) ? ws[lane] : 0, ui = u;
#pragma unroll
        for (int off = 1; off < 8; off <<= 1) {
            int t = __shfl_up_sync(0xffffffffu, ui, off);
            if (lane >= off) ui += t;
        }
        if (lane < 8) ws[lane] = ui - u;
        if (lane == 7) tot = ui;
    }
    __syncthreads();
    int excl = ws[wid] + incl - v;
    if (tid < 196) g_part[tid] = excl;
    if (tid == 0) g_rowptr[NN] = tot;
}
__global__ void scan_fin() {
    int tid = threadIdx.x, lane = tid & 31, wid = tid >> 5;
    int idx = blockIdx.x * 256 + tid;
    int v = (idx < NN) ? g_cnt[idx] : 0;
    int incl = v;
#pragma unroll
    for (int off = 1; off < 32; off <<= 1) {
        int t = __shfl_up_sync(0xffffffffu, incl, off);
        if (lane >= off) incl += t;
    }
    __shared__ int ws[8];
    if (lane == 31) ws[wid] = incl;
    __syncthreads();
    if (wid == 0) {
        int u = (lane < 8) ? ws[lane] : 0, ui = u;
#pragma unroll
        for (int off = 1; off < 8; off <<= 1) {
            int t = __shfl_up_sync(0xffffffffu, ui, off);
            if (lane >= off) ui += t;
        }
        if (lane < 8) ws[lane] = ui - u;
    }
    __syncthreads();
    int excl = g_part[blockIdx.x] + ws[wid] + incl - v;
    if (idx < NN) { g_rowptr[idx] = excl; g_wr[idx] = excl; }
}
__global__ void fill_kernel(const void* __restrict__ ei) {
    int e = blockIdx.x * blockDim.x + threadIdx.x;
    if (e >= EE) return;
    int src = edge_at(ei, e);
    int dst = edge_at(ei, EE + e);
    if ((unsigned)dst >= NN || (unsigned)src >= NN) return;
    int pos = atomicAdd(&g_wr[dst], 1);
    if ((unsigned)pos < EE) g_col[pos] = src;
}
__global__ void degdis_kernel() {
    int i = blockIdx.x * blockDim.x + threadIdx.x;
    if (i >= NN) return;
    int c = g_cnt[i];
    g_dis[i] = (c > 0) ? rsqrtf((float)c) : 0.f;
}
__global__ void zero_lsld_kernel() {
    int i = blockIdx.x * blockDim.x + threadIdx.x;
    if (i < NN) { g_ls[i] = 0.f; g_ld[i] = 0.f; }
}

// ==================== weight conversion ====================
struct WP { const float* p[16]; };
__global__ void convert_w_kernel(WP wp) {
    int mat = blockIdx.y;
    int i = blockIdx.x * 256 + threadIdx.x;
    float v = wp.p[mat][i];
    __nv_bfloat16 h = __float2bfloat16(v);
    __nv_bfloat16 l = __float2bfloat16(v - __bfloat162float(h));
    g_wh[mat * 16384 + i] = h;
    g_wl[mat * 16384 + i] = l;
}

// ==================== GAT projection vectors ====================
__global__ void gatvec_kernel(const float* __restrict__ gat_W,
                              const float* __restrict__ gat_as,
                              const float* __restrict__ gat_ad) {
    int l = blockIdx.y, which = blockIdx.x, k = threadIdx.x;
    const float* W = gat_W + l * HH * HH;
    const float* a = (which ? gat_ad : gat_as) + l * HH;
    float acc = 0.f;
    for (int n = 0; n < HH; n++) acc += W[n * HH + k] * a[n];
    (which ? g_vd : g_vs)[l * HH + k] = acc;
}

// ==================== edge aggregation (4-way unrolled gather, MUFU exp) ====================
template <int CUR>
__global__ void __launch_bounds__(256) agg2_kernel(const float* __restrict__ eps_ptr) {
    const float* cur = buf<CUR>();
    int n = (blockIdx.x * blockDim.x + threadIdx.x) >> 5;
    int lane = threadIdx.x & 31;
    if (n >= NN) return;
    int start = g_rowptr[n], end = g_rowptr[n + 1];
    float ldn = g_ld[n];

    float m = -INFINITY, sd = 0.f;
    for (int i = start + lane; i < end; i += 32) {
        int s = g_col[i];
        float l = g_ls[s] + ldn;
        l = (l >= 0.f) ? l : 0.2f * l;
        m = fmaxf(m, l);
        sd += g_dis[s];
    }
#pragma unroll
    for (int off = 16; off; off >>= 1) {
        m = fmaxf(m, __shfl_xor_sync(0xffffffffu, m, off));
        sd += __shfl_xor_sync(0xffffffffu, sd, off);
    }

    float4 S1 = make_float4(0, 0, 0, 0), Sd = S1, Sa = S1;
    float z = 0.f;
    int i = start;
    for (; i + 3 < end; i += 4) {
        int s0 = g_col[i], s1 = g_col[i + 1], s2 = g_col[i + 2], s3 = g_col[i + 3];
        float l0 = g_ls[s0] + ldn; l0 = (l0 >= 0.f) ? l0 : 0.2f * l0;
        float l1 = g_ls[s1] + ldn; l1 = (l1 >= 0.f) ? l1 : 0.2f * l1;
        float l2 = g_ls[s2] + ldn; l2 = (l2 >= 0.f) ? l2 : 0.2f * l2;
        float l3 = g_ls[s3] + ldn; l3 = (l3 >= 0.f) ? l3 : 0.2f * l3;
        float e0 = __expf(l0 - m), e1 = __expf(l1 - m);
        float e2 = __expf(l2 - m), e3 = __expf(l3 - m);
        float d0 = g_dis[s0], d1 = g_dis[s1], d2 = g_dis[s2], d3 = g_dis[s3];
        float4 a0 = *(const float4*)&cur[(size_t)s0 * HH + lane * 4];
        float4 a1 = *(const float4*)&cur[(size_t)s1 * HH + lane * 4];
        float4 a2 = *(const float4*)&cur[(size_t)s2 * HH + lane * 4];
        float4 a3 = *(const float4*)&cur[(size_t)s3 * HH + lane * 4];
        z += (e0 + e1) + (e2 + e3);
        S1.x += (a0.x + a1.x) + (a2.x + a3.x);
        S1.y += (a0.y + a1.y) + (a2.y + a3.y);
        S1.z += (a0.z + a1.z) + (a2.z + a3.z);
        S1.w += (a0.w + a1.w) + (a2.w + a3.w);
        Sd.x += (d0 * a0.x + d1 * a1.x) + (d2 * a2.x + d3 * a3.x);
        Sd.y += (d0 * a0.y + d1 * a1.y) + (d2 * a2.y + d3 * a3.y);
        Sd.z += (d0 * a0.z + d1 * a1.z) + (d2 * a2.z + d3 * a3.z);
        Sd.w += (d0 * a0.w + d1 * a1.w) + (d2 * a2.w + d3 * a3.w);
        Sa.x += (e0 * a0.x + e1 * a1.x) + (e2 * a2.x + e3 * a3.x);
        Sa.y += (e0 * a0.y + e1 * a1.y) + (e2 * a2.y + e3 * a3.y);
        Sa.z += (e0 * a0.z + e1 * a1.z) + (e2 * a2.z + e3 * a3.z);
        Sa.w += (e0 * a0.w + e1 * a1.w) + (e2 * a2.w + e3 * a3.w);
    }
    for (; i < end; i++) {
        int s = g_col[i];
        float l = g_ls[s] + ldn;
        l = (l >= 0.f) ? l : 0.2f * l;
        float e = __expf(l - m);
        float ds = g_dis[s];
        float4 x4 = *(const float4*)&cur[(size_t)s * HH + lane * 4];
        z += e;
        S1.x += x4.x; S1.y += x4.y; S1.z += x4.z; S1.w += x4.w;
        Sd.x += ds * x4.x; Sd.y += ds * x4.y; Sd.z += ds * x4.z; Sd.w += ds * x4.w;
        Sa.x += e * x4.x; Sa.y += e * x4.y; Sa.z += e * x4.z; Sa.w += e * x4.w;
    }

    float deg = (float)(end - start);
    float inv = 1.f / fmaxf(deg, 1.f);
    float eps1 = 1.f + *eps_ptr;
    float disn = g_dis[n];
    float zinv = 1.f / (z + 1e-16f);
    float4 c4 = *(const float4*)&cur[(size_t)n * HH + lane * 4];
    size_t o = (size_t)n * HH + lane * 4;

    float4 t;
    t.x = S1.x * inv; t.y = S1.y * inv; t.z = S1.z * inv; t.w = S1.w * inv;
    *(float4*)&g_aggn[o] = t;
    t.x = eps1 * c4.x + S1.x; t.y = eps1 * c4.y + S1.y;
    t.z = eps1 * c4.z + S1.z; t.w = eps1 * c4.w + S1.w;
    *(float4*)&g_ginin[o] = t;
    t.x = disn * Sd.x; t.y = disn * Sd.y; t.z = disn * Sd.z; t.w = disn * Sd.w;
    *(float4*)&g_gcnin[o] = t;
    t.x = zinv * Sa.x; t.y = zinv * Sa.y; t.z = zinv * Sa.z; t.w = zinv * Sa.w;
    *(float4*)&g_gatin[o] = t;
    if (lane == 0) g_sn[n] = disn * sd;
}

// ==================== mma helpers ====================
struct MmaAcc { float a[2][8][4]; };
__device__ __forceinline__ void mma_zero(MmaAcc& A) {
#pragma unroll
    for (int i = 0; i < 2; i++)
#pragma unroll
        for (int j = 0; j < 8; j++)
#pragma unroll
            for (int k = 0; k < 4; k++) A.a[i][j][k] = 0.f;
}

__device__ __forceinline__ void stage_A(const float* __restrict__ A, int row0, int tid,
                                        __nv_bfloat16* sAhi, __nv_bfloat16* sAlo) {
    const float4* Ag = (const float4*)A;
#pragma unroll
    for (int it = 0; it < 16; it++) {
        int idx = tid + it * 256;
        int r = idx >> 5, c4 = idx & 31;
        int gr = row0 + r;
        float4 v = (gr < NN) ? Ag[(size_t)gr * 32 + c4] : make_float4(0, 0, 0, 0);
        __nv_bfloat16 hx = __float2bfloat16(v.x), hy = __float2bfloat16(v.y);
        __nv_bfloat16 hz = __float2bfloat16(v.z), hw = __float2bfloat16(v.w);
        unsigned h0 = pack2bf(hx, hy), h1 = pack2bf(hz, hw);
        unsigned l0 = pack2bf(__float2bfloat16(v.x - __bfloat162float(hx)),
                              __float2bfloat16(v.y - __bfloat162float(hy)));
        unsigned l1 = pack2bf(__float2bfloat16(v.z - __bfloat162float(hz)),
                              __float2bfloat16(v.w - __bfloat162float(hw)));
        *(uint2*)&sAhi[r * 136 + c4 * 4] = make_uint2(h0, h1);
        *(uint2*)&sAlo[r * 136 + c4 * 4] = make_uint2(l0, l1);
    }
}

__device__ __forceinline__ void issue_w_chunk(int tid, uint32_t sWU_,
                                              const __nv_bfloat16* WHp,
                                              const __nv_bfloat16* WLp, int c) {
    int kh = c >> 1;
    const __nv_bfloat16* Wsrc = (c & 1) ? WLp : WHp;
#pragma unroll
    for (int it = 0; it < 4; it++) {
        int idx = tid + it * 256;
        int rrow = idx >> 3, c8 = (idx & 7) * 8;
        uint32_t d = sWU_ + (uint32_t)(rrow * 72 + c8) * 2;
        const void* s = Wsrc + rrow * 128 + kh * 64 + c8;
        asm volatile("cp.async.cg.shared.global [%0], [%1], 16;" :: "r"(d), "l"(s));
    }
    asm volatile("cp.async.commit_group;" ::: "memory");
}

// ==================== GEMM: M=128 tile, cp.async double-buffered W, full chunk unroll ====================
#define SMEM_GEMM 107008
template <int SA1, int WI1, int SA2, int WI2, int DST, int BMODE, int CMODE, int LSLDV, int OP>
__global__ void __launch_bounds__(256, 2)
gemm_mma(const float* __restrict__ A1p, const float* __restrict__ bias, int l) {
    extern __shared__ char smem[];
    __nv_bfloat16* sAhi = (__nv_bfloat16*)smem;
    __nv_bfloat16* sAlo = sAhi + 128 * 136;
    __nv_bfloat16* sW0  = sAlo + 128 * 136;
    __nv_bfloat16* sW1  = sW0 + 128 * 72;
    float* sbias = (float*)(sW1 + 128 * 72);
    const int tid = threadIdx.x, lane = tid & 31, warp = tid >> 5;
    const int wm = warp >> 1, wn = warp & 1;
    const int row0 = blockIdx.x * 128;
    if (BMODE && tid < 128) sbias[tid] = bias[tid];
    const uint32_t sAhiU = smem_u32(sAhi), sAloU = smem_u32(sAlo);
    const uint32_t sW0U = smem_u32(sW0), sW1U = smem_u32(sW1);

    MmaAcc acc;
    mma_zero(acc);

    const int npass = (SA2 >= 0) ? 2 : 1;
#pragma unroll 1
    for (int pass = 0; pass < npass; pass++) {
        const float* A = (pass == 0)
            ? ((SA1 < 0) ? A1p : buf<(SA1 < 0) ? 0 : SA1>())
            : buf<(SA2 < 0) ? 0 : SA2>();
        const int wi = (pass == 0) ? WI1 : ((WI2 < 0) ? 0 : WI2);
        const __nv_bfloat16* WHp = g_wh + wi * 16384;
        const __nv_bfloat16* WLp = g_wl + wi * 16384;

        __syncthreads();
        issue_w_chunk(tid, sW0U, WHp, WLp, 0);
        stage_A(A, row0, tid, sAhi, sAlo);

#pragma unroll
        for (int c = 0; c < 4; c++) {
            asm volatile("cp.async.wait_group 0;" ::: "memory");
            __syncthreads();
            if (c < 3) issue_w_chunk(tid, (c & 1) ? sW0U : sW1U, WHp, WLp, c + 1);
            const uint32_t sWU = (c & 1) ? sW1U : sW0U;
            const int kh = c >> 1, wv = c & 1;
#pragma unroll
            for (int ks = 0; ks < 4; ks++) {
                int k0 = ks * 16;
                uint32_t bfr[4][4];
#pragma unroll
                for (int p = 0; p < 4; p++) {
                    int grp = lane >> 3, rr = lane & 7;
                    int row = wn * 64 + p * 16 + ((grp >> 1) << 3) + rr;
                    int col = k0 + ((grp & 1) << 3);
                    uint32_t ad = sWU + (row * 72 + col) * 2;
                    asm volatile(
                        "ldmatrix.sync.aligned.m8n8.x4.shared.b16 {%0,%1,%2,%3}, [%4];"
                        : "=r"(bfr[p][0]), "=r"(bfr[p][1]), "=r"(bfr[p][2]), "=r"(bfr[p][3])
                        : "r"(ad));
                }
                uint32_t af[2][4];
#pragma unroll
                for (int mi = 0; mi < 2; mi++) {
                    int grp = lane >> 3, rr = lane & 7;
                    int row = wm * 32 + mi * 16 + ((grp & 1) << 3) + rr;
                    int col = kh * 64 + k0 + ((grp >> 1) << 3);
                    uint32_t ad = sAhiU + (row * 136 + col) * 2;
                    asm volatile(
                        "ldmatrix.sync.aligned.m8n8.x4.shared.b16 {%0,%1,%2,%3}, [%4];"
                        : "=r"(af[mi][0]), "=r"(af[mi][1]), "=r"(af[mi][2]), "=r"(af[mi][3])
                        : "r"(ad));
                }
#pragma unroll
                for (int mi = 0; mi < 2; mi++)
#pragma unroll
                    for (int ni = 0; ni < 8; ni++) {
                        uint32_t b0 = bfr[ni >> 1][(ni & 1) * 2];
                        uint32_t b1 = bfr[ni >> 1][(ni & 1) * 2 + 1];
                        asm volatile(
                            "mma.sync.aligned.m16n8k16.row.col.f32.bf16.bf16.f32 "
                            "{%0,%1,%2,%3}, {%4,%5,%6,%7}, {%8,%9}, {%0,%1,%2,%3};"
                            : "+f"(acc.a[mi][ni][0]), "+f"(acc.a[mi][ni][1]),
                              "+f"(acc.a[mi][ni][2]), "+f"(acc.a[mi][ni][3])
                            : "r"(af[mi][0]), "r"(af[mi][1]), "r"(af[mi][2]), "r"(af[mi][3]),
                              "r"(b0), "r"(b1));
                    }
                if (wv == 0) {
                    uint32_t al[2][4];
#pragma unroll
                    for (int mi = 0; mi < 2; mi++) {
                        int grp = lane >> 3, rr = lane & 7;
                        int row = wm * 32 + mi * 16 + ((grp & 1) << 3) + rr;
                        int col = kh * 64 + k0 + ((grp >> 1) << 3);
                        uint32_t ad = sAloU + (row * 136 + col) * 2;
                        asm volatile(
                            "ldmatrix.sync.aligned.m8n8.x4.shared.b16 {%0,%1,%2,%3}, [%4];"
                            : "=r"(al[mi][0]), "=r"(al[mi][1]), "=r"(al[mi][2]), "=r"(al[mi][3])
                            : "r"(ad));
                    }
#pragma unroll
                    for (int mi = 0; mi < 2; mi++)
#pragma unroll
                        for (int ni = 0; ni < 8; ni++) {
                            uint32_t b0 = bfr[ni >> 1][(ni & 1) * 2];
                            uint32_t b1 = bfr[ni >> 1][(ni & 1) * 2 + 1];
                            asm volatile(
                                "mma.sync.aligned.m16n8k16.row.col.f32.bf16.bf16.f32 "
                                "{%0,%1,%2,%3}, {%4,%5,%6,%7}, {%8,%9}, {%0,%1,%2,%3};"
                                : "+f"(acc.a[mi][ni][0]), "+f"(acc.a[mi][ni][1]),
                                  "+f"(acc.a[mi][ni][2]), "+f"(acc.a[mi][ni][3])
                                : "r"(al[mi][0]), "r"(al[mi][1]), "r"(al[mi][2]), "r"(al[mi][3]),
                                  "r"(b0), "r"(b1));
                        }
                }
            }
        }
    }
    __syncthreads();

    // ---------- epilogue ----------
    const float w = (CMODE >= 1) ? g_naw[l * 4 + OP] : 0.f;
    const int lv = (LSLDV >= 0) ? LSLDV : 0;
    const float* vsv = g_vs + lv * HH;
    const float* vdv = g_vd + lv * HH;
    float* C = buf<DST>();
#pragma unroll
    for (int mi = 0; mi < 2; mi++) {
        int rA = row0 + wm * 32 + mi * 16 + (lane >> 2);
        int rB = rA + 8;
        float snA = 0.f, snB = 0.f;
        if (BMODE == 2) {
            snA = (rA < NN) ? g_sn[rA] : 0.f;
            snB = (rB < NN) ? g_sn[rB] : 0.f;
        }
        float psA = 0.f, pdA = 0.f, psB = 0.f, pdB = 0.f;
#pragma unroll
        for (int ni = 0; ni < 8; ni++) {
            int col = wn * 64 + ni * 8 + (lane & 3) * 2;
            float2 vA = make_float2(acc.a[mi][ni][0], acc.a[mi][ni][1]);
            float2 vB = make_float2(acc.a[mi][ni][2], acc.a[mi][ni][3]);
            if (BMODE == 1) {
                vA.x += sbias[col]; vA.y += sbias[col + 1];
                vB.x += sbias[col]; vB.y += sbias[col + 1];
            }
            if (BMODE == 2) {
                vA.x += snA * sbias[col]; vA.y += snA * sbias[col + 1];
                vB.x += snB * sbias[col]; vB.y += snB * sbias[col + 1];
            }
            if (CMODE >= 1) {
                vA.x = w * eluf(vA.x); vA.y = w * eluf(vA.y);
                vB.x = w * eluf(vB.x); vB.y = w * eluf(vB.y);
            }
            if (rA < NN) {
                float2* cp = (float2*)&C[(size_t)rA * HH + col];
                if (CMODE == 2) { float2 o = *cp; vA.x += o.x; vA.y += o.y; }
                *cp = vA;
            }
            if (rB < NN) {
                float2* cp = (float2*)&C[(size_t)rB * HH + col];
                if (CMODE == 2) { float2 o = *cp; vB.x += o.x; vB.y += o.y; }
                *cp = vB;
            }
            if (LSLDV >= 0) {
                float s0 = __ldg(&vsv[col]), s1 = __ldg(&vsv[col + 1]);
                float d0 = __ldg(&vdv[col]), d1 = __ldg(&vdv[col + 1]);
                psA += vA.x * s0 + vA.y * s1; pdA += vA.x * d0 + vA.y * d1;
                psB += vB.x * s0 + vB.y * s1; pdB += vB.x * d0 + vB.y * d1;
            }
        }
        if (LSLDV >= 0) {
            psA += __shfl_xor_sync(0xffffffffu, psA, 1);
            psA += __shfl_xor_sync(0xffffffffu, psA, 2);
            pdA += __shfl_xor_sync(0xffffffffu, pdA, 1);
            pdA += __shfl_xor_sync(0xffffffffu, pdA, 2);
            psB += __shfl_xor_sync(0xffffffffu, psB, 1);
            psB += __shfl_xor_sync(0xffffffffu, psB, 2);
            pdB += __shfl_xor_sync(0xffffffffu, pdB, 1);
            pdB += __shfl_xor_sync(0xffffffffu, pdB, 2);
            if ((lane & 3) == 0) {
                if (rA < NN) { atomicAdd(&g_ls[rA], psA); atomicAdd(&g_ld[rA], pdA); }
                if (rB < NN) { atomicAdd(&g_ls[rB], psB); atomicAdd(&g_ld[rB], pdB); }
            }
        }
    }
}

// ==================== fused x5 + node classifier ====================
__global__ void __launch_bounds__(256)
nc_fused_kernel(const float* __restrict__ Wnc, const float* __restrict__ bnc,
                float* __restrict__ out) {
    __shared__ float Ws[NC * 132];
    __shared__ float bs[NC];
    int tid = threadIdx.x;
    for (int i = tid; i < NC * HH; i += 256) {
        int j = i / HH, k = i % HH;
        Ws[j * 132 + k] = Wnc[i];
    }
    if (tid < NC) bs[tid] = bnc[tid];
    __syncthreads();
    int row = blockIdx.x * 64 + (tid >> 2);
    int c0 = (tid & 3) * 10;
    if (row >= NN) return;
    float sc0 = g_scw[1], sc1 = g_scw[3];
    float la0 = g_law[0], la1 = g_law[1], la2 = g_law[2];
    float acc[10];
#pragma unroll
    for (int j = 0; j < 10; j++) acc[j] = 0.f;
    const float* r3 = &g_x3[(size_t)row * HH];
    const float* r1 = &g_x1[(size_t)row * HH];
    const float* r2 = &g_x2[(size_t)row * HH];
    for (int k = 0; k < HH; k += 4) {
        float4 a = *(const float4*)&r3[k];
        float4 b = *(const float4*)&r1[k];
        float4 c = *(const float4*)&r2[k];
        float x5v[4];
#define ONE(i, f)                                                               \
        {                                                                       \
            float bb = sc0 * b.f, cc = sc1 * c.f;                               \
            float mx = fmaxf(fmaxf(a.f, bb), cc);                               \
            float sm = a.f + bb + cc;                                           \
            float mn = sm * (1.f / 3.f);                                        \
            x5v[i] = la0 * fmaxf(mx, 0.f) + la1 * fmaxf(mn, 0.f) + la2 * fmaxf(sm, 0.f); \
        }
        ONE(0, x) ONE(1, y) ONE(2, z) ONE(3, w)
#undef ONE
#pragma unroll
        for (int j = 0; j < 10; j++) {
            acc[j] += x5v[0] * Ws[(c0 + j) * 132 + k]     + x5v[1] * Ws[(c0 + j) * 132 + k + 1]
                    + x5v[2] * Ws[(c0 + j) * 132 + k + 2] + x5v[3] * Ws[(c0 + j) * 132 + k + 3];
        }
    }
#pragma unroll
    for (int j = 0; j < 10; j++) out[row * NC + c0 + j] = acc[j] + bs[c0 + j];
}

// ==================== host ====================
static const int TPB = 256;
static const int GGB = (NN + 127) / 128;   // 391
static const int SB  = (NN + 255) / 256;   // 196

#define LAUNCH_GEMM(SA1, WI1, SA2, WI2, DST, BM_, CM_, LV_, OP_, Aptr, Bptr, lArg)    \
    do {                                                                              \
        cudaFuncSetAttribute(gemm_mma<SA1, WI1, SA2, WI2, DST, BM_, CM_, LV_, OP_>,   \
                             cudaFuncAttributeMaxDynamicSharedMemorySize, SMEM_GEMM); \
        gemm_mma<SA1, WI1, SA2, WI2, DST, BM_, CM_, LV_, OP_>                         \
            <<<GGB, 256, SMEM_GEMM>>>(Aptr, Bptr, lArg);                              \
    } while (0)

template <int CUR, int DST, int L>
static void run_layer(const float* gcn_b, const float* gin_b, const float* gin_eps) {
    agg2_kernel<CUR><<<(NN * 32 + TPB - 1) / TPB, TPB>>>(gin_eps + L);
    // GCN: first combine write
    LAUNCH_GEMM(4, 1 + L, -1, -1, DST, 2, 1, -1, 0, nullptr, gcn_b + L * HH, L);
    // GAT: RMW
    LAUNCH_GEMM(5, 13 + L, -1, -1, DST, 0, 2, -1, 3, nullptr, nullptr, L);
    // SAGE (dual): RMW
    LAUNCH_GEMM(CUR, 4 + L, 6, 7 + L, DST, 0, 2, -1, 1, nullptr, nullptr, L);
    // GIN: RMW, final -> also produces lsld for next layer
    if (L < 2) zero_lsld_kernel<<<SB, 256>>>();
    constexpr int LV = (L < 2) ? (L + 1) : -1;
    LAUNCH_GEMM(7, 10 + L, -1, -1, DST, 1, 2, LV, 2, nullptr, gin_b + L * HH, L);
}

extern "C" void kernel_launch(void* const* d_in, const int* in_sizes, int n_in,
                              void* d_out, int out_size) {
    const float* x       = (const float*)d_in[0];
    const void*  ei      = d_in[1];
    const float* na_a    = (const float*)d_in[2];
    const float* sc_a    = (const float*)d_in[3];
    const float* la_a    = (const float*)d_in[4];
    const float* lin1_W  = (const float*)d_in[5];
    const float* lin1_b  = (const float*)d_in[6];
    const float* gcn_W   = (const float*)d_in[7];
    const float* gcn_b   = (const float*)d_in[8];
    const float* sage_Ws = (const float*)d_in[9];
    const float* sage_Wn = (const float*)d_in[10];
    const float* gin_W   = (const float*)d_in[11];
    const float* gin_b   = (const float*)d_in[12];
    const float* gin_eps = (const float*)d_in[13];
    const float* gat_W   = (const float*)d_in[14];
    const float* gat_as  = (const float*)d_in[15];
    const float* gat_ad  = (const float*)d_in[16];
    const float* nc_W    = (const float*)d_in[17];
    const float* nc_b    = (const float*)d_in[18];
    float*       out     = (float*)d_out;

    WP wp;
    wp.p[0] = lin1_W;
    for (int l = 0; l < 3; l++) {
        wp.p[1 + l]  = gcn_W + l * HH * HH;
        wp.p[4 + l]  = sage_Ws + l * HH * HH;
        wp.p[7 + l]  = sage_Wn + l * HH * HH;
        wp.p[10 + l] = gin_W + l * HH * HH;
        wp.p[13 + l] = gat_W + l * HH * HH;
    }
    // order: lin1 GEMM is the 4th launch (ncu captures launch #4)
    convert_w_kernel<<<dim3(64, 16), 256>>>(wp);                       // 1
    gatvec_kernel<<<dim3(2, 3), 128>>>(gat_W, gat_as, gat_ad);         // 2
    zero_lsld_kernel<<<SB, 256>>>();                                   // 3
    LAUNCH_GEMM(-1, 0, -1, -1, 0, 1, 0, 0, 0, x, lin1_b, 0);           // 4  <- profiled
    detect_kernel<<<1, 512>>>((const int*)ei);                         // 5
    zero_cnt_kernel<<<SB, 256>>>();                                    // 6
    count_kernel<<<(EE + TPB - 1) / TPB, TPB>>>(ei);                   // 7
    scan_part<<<SB, 256>>>();
    scan_mid<<<1, 256>>>();
    scan_fin<<<SB, 256>>>();
    fill_kernel<<<(EE + TPB - 1) / TPB, TPB>>>(ei);
    degdis_kernel<<<SB, 256>>>();
    softmax_small_kernel<<<1, 32>>>(na_a, sc_a, la_a);

    run_layer<0, 1, 0>(gcn_b, gin_b, gin_eps);
    run_layer<1, 2, 1>(gcn_b, gin_b, gin_eps);
    run_layer<2, 3, 2>(gcn_b, gin_b, gin_eps);

    nc_fused_kernel<<<(NN + 63) / 64, 256>>>(nc_W, nc_b, out);
}

// round 16
// speedup vs baseline: 1.3117x; 1.3117x over previous
#include <cuda_runtime.h>
#include <cuda_bf16.h>
#include <math.h>
#include <stdint.h>

#define NN 50000
#define EE 800000
#define HH 128
#define NC 40

// ==================== scratch ====================
__device__ int   g_is64;
__device__ int   g_cnt[NN];
__device__ int   g_part[256];
__device__ int   g_rowptr[NN + 1];
__device__ int   g_wr[NN];
__device__ int   g_col[EE];
__device__ float g_dis[NN];
__device__ float g_sn[NN];
__device__ float g_ls[NN], g_ld[NN];
__device__ float g_vs[3 * HH], g_vd[3 * HH];
__device__ float g_h0[NN * HH];
__device__ float g_x1[NN * HH], g_x2[NN * HH], g_x3[NN * HH];
__device__ float g_gcnin[NN * HH], g_gatin[NN * HH];
__device__ float g_aggn[NN * HH], g_ginin[NN * HH];
__device__ float g_naw[12], g_scw[4], g_law[3];
__device__ __nv_bfloat16 g_wh[16 * 16384];
__device__ __nv_bfloat16 g_wl[16 * 16384];

template <int ID>
__device__ __forceinline__ float* buf() {
    if (ID == 0)  return g_h0;
    if (ID == 1)  return g_x1;
    if (ID == 2)  return g_x2;
    if (ID == 3)  return g_x3;
    if (ID == 4)  return g_gcnin;
    if (ID == 5)  return g_gatin;
    if (ID == 6)  return g_aggn;
    return g_ginin;
}

__device__ __forceinline__ float eluf(float x) { return x > 0.f ? x : expm1f(x); }
__device__ __forceinline__ int edge_at(const void* p, int idx) {
    if (g_is64) return (int)((const long long*)p)[idx];
    return ((const int*)p)[idx];
}
__device__ __forceinline__ uint32_t smem_u32(const void* p) {
    uint32_t a;
    asm("{ .reg .u64 t; cvta.to.shared.u64 t, %1; cvt.u32.u64 %0, t; }" : "=r"(a) : "l"(p));
    return a;
}
__device__ __forceinline__ unsigned pack2bf(__nv_bfloat16 a, __nv_bfloat16 b) {
    return (unsigned)__bfloat16_as_ushort(a) | ((unsigned)__bfloat16_as_ushort(b) << 16);
}

// ==================== edge dtype detection ====================
__global__ void detect_kernel(const int* __restrict__ p) {
    __shared__ int nz;
    if (threadIdx.x == 0) nz = 0;
    __syncthreads();
    int local = 0;
    for (int i = threadIdx.x * 2 + 1; i < 8192; i += 2 * blockDim.x)
        if (p[i] != 0) local = 1;
    if (local) atomicOr(&nz, 1);
    __syncthreads();
    if (threadIdx.x == 0) g_is64 = nz ? 0 : 1;
}

// ==================== tiny softmaxes ====================
__global__ void softmax_small_kernel(const float* __restrict__ na,
                                     const float* __restrict__ sc,
                                     const float* __restrict__ la) {
    if (threadIdx.x != 0 || blockIdx.x != 0) return;
    for (int r = 0; r < 3; r++) {
        float m = -1e30f;
        for (int j = 0; j < 4; j++) m = fmaxf(m, na[r * 4 + j]);
        float z = 0.f, e[4];
        for (int j = 0; j < 4; j++) { e[j] = expf(na[r * 4 + j] - m); z += e[j]; }
        for (int j = 0; j < 4; j++) g_naw[r * 4 + j] = e[j] / z;
    }
    for (int r = 0; r < 2; r++) {
        float m = fmaxf(sc[r * 2], sc[r * 2 + 1]);
        float e0 = expf(sc[r * 2] - m), e1 = expf(sc[r * 2 + 1] - m);
        g_scw[r * 2] = e0 / (e0 + e1);
        g_scw[r * 2 + 1] = e1 / (e0 + e1);
    }
    {
        float m = fmaxf(fmaxf(la[0], la[1]), la[2]);
        float e0 = expf(la[0] - m), e1 = expf(la[1] - m), e2 = expf(la[2] - m);
        float z = e0 + e1 + e2;
        g_law[0] = e0 / z; g_law[1] = e1 / z; g_law[2] = e2 / z;
    }
}

// ==================== CSR build ====================
__global__ void zero_cnt_kernel() {
    int i = blockIdx.x * blockDim.x + threadIdx.x;
    if (i < NN) g_cnt[i] = 0;
}
__global__ void count_kernel(const void* __restrict__ ei) {
    int e = blockIdx.x * blockDim.x + threadIdx.x;
    if (e >= EE) return;
    int dst = edge_at(ei, EE + e);
    if ((unsigned)dst >= NN) return;
    atomicAdd(&g_cnt[dst], 1);
}
__global__ void scan_part() {
    int tid = threadIdx.x, lane = tid & 31, wid = tid >> 5;
    int idx = blockIdx.x * 256 + tid;
    int v = (idx < NN) ? g_cnt[idx] : 0;
#pragma unroll
    for (int off = 16; off; off >>= 1) v += __shfl_xor_sync(0xffffffffu, v, off);
    __shared__ int ws[8];
    if (lane == 0) ws[wid] = v;
    __syncthreads();
    if (tid == 0) {
        int s = 0;
#pragma unroll
        for (int i = 0; i < 8; i++) s += ws[i];
        g_part[blockIdx.x] = s;
    }
}
__global__ void scan_mid() {
    int tid = threadIdx.x, lane = tid & 31, wid = tid >> 5;
    int v = (tid < 196) ? g_part[tid] : 0;
    int incl = v;
#pragma unroll
    for (int off = 1; off < 32; off <<= 1) {
        int t = __shfl_up_sync(0xffffffffu, incl, off);
        if (lane >= off) incl += t;
    }
    __shared__ int ws[8];
    __shared__ int tot;
    if (lane == 31) ws[wid] = incl;
    __syncthreads();
    if (wid == 0) {
        int u = (lane < 8) ? ws[lane] : 0, ui = u;
#pragma unroll
        for (int off = 1; off < 8; off <<= 1) {
            int t = __shfl_up_sync(0xffffffffu, ui, off);
            if (lane >= off) ui += t;
        }
        if (lane < 8) ws[lane] = ui - u;
        if (lane == 7) tot = ui;
    }
    __syncthreads();
    int excl = ws[wid] + incl - v;
    if (tid < 196) g_part[tid] = excl;
    if (tid == 0) g_rowptr[NN] = tot;
}
__global__ void scan_fin() {
    int tid = threadIdx.x, lane = tid & 31, wid = tid >> 5;
    int idx = blockIdx.x * 256 + tid;
    int v = (idx < NN) ? g_cnt[idx] : 0;
    int incl = v;
#pragma unroll
    for (int off = 1; off < 32; off <<= 1) {
        int t = __shfl_up_sync(0xffffffffu, incl, off);
        if (lane >= off) incl += t;
    }
    __shared__ int ws[8];
    if (lane == 31) ws[wid] = incl;
    __syncthreads();
    if (wid == 0) {
        int u = (lane < 8) ? ws[lane] : 0, ui = u;
#pragma unroll
        for (int off = 1; off < 8; off <<= 1) {
            int t = __shfl_up_sync(0xffffffffu, ui, off);
            if (lane >= off) ui += t;
        }
        if (lane < 8) ws[lane] = ui - u;
    }
    __syncthreads();
    int excl = g_part[blockIdx.x] + ws[wid] + incl - v;
    if (idx < NN) { g_rowptr[idx] = excl; g_wr[idx] = excl; }
}
__global__ void fill_kernel(const void* __restrict__ ei) {
    int e = blockIdx.x * blockDim.x + threadIdx.x;
    if (e >= EE) return;
    int src = edge_at(ei, e);
    int dst = edge_at(ei, EE + e);
    if ((unsigned)dst >= NN || (unsigned)src >= NN) return;
    int pos = atomicAdd(&g_wr[dst], 1);
    if ((unsigned)pos < EE) g_col[pos] = src;
}
__global__ void degdis_kernel() {
    int i = blockIdx.x * blockDim.x + threadIdx.x;
    if (i >= NN) return;
    int c = g_cnt[i];
    g_dis[i] = (c > 0) ? rsqrtf((float)c) : 0.f;
}
__global__ void zero_lsld_kernel() {
    int i = blockIdx.x * blockDim.x + threadIdx.x;
    if (i < NN) { g_ls[i] = 0.f; g_ld[i] = 0.f; }
}

// ==================== weight conversion ====================
struct WP { const float* p[16]; };
__global__ void convert_w_kernel(WP wp) {
    int mat = blockIdx.y;
    int i = blockIdx.x * 256 + threadIdx.x;
    float v = wp.p[mat][i];
    __nv_bfloat16 h = __float2bfloat16(v);
    __nv_bfloat16 l = __float2bfloat16(v - __bfloat162float(h));
    g_wh[mat * 16384 + i] = h;
    g_wl[mat * 16384 + i] = l;
}

// ==================== GAT projection vectors ====================
__global__ void gatvec_kernel(const float* __restrict__ gat_W,
                              const float* __restrict__ gat_as,
                              const float* __restrict__ gat_ad) {
    int l = blockIdx.y, which = blockIdx.x, k = threadIdx.x;
    const float* W = gat_W + l * HH * HH;
    const float* a = (which ? gat_ad : gat_as) + l * HH;
    float acc = 0.f;
    for (int n = 0; n < HH; n++) acc += W[n * HH + k] * a[n];
    (which ? g_vd : g_vs)[l * HH + k] = acc;
}

// ==================== edge aggregation (2-way unrolled gather, MUFU exp) ====================
template <int CUR>
__global__ void __launch_bounds__(256) agg2_kernel(const float* __restrict__ eps_ptr) {
    const float* cur = buf<CUR>();
    int n = (blockIdx.x * blockDim.x + threadIdx.x) >> 5;
    int lane = threadIdx.x & 31;
    if (n >= NN) return;
    int start = g_rowptr[n], end = g_rowptr[n + 1];
    float ldn = g_ld[n];

    float m = -INFINITY, sd = 0.f;
    for (int i = start + lane; i < end; i += 32) {
        int s = g_col[i];
        float l = g_ls[s] + ldn;
        l = (l >= 0.f) ? l : 0.2f * l;
        m = fmaxf(m, l);
        sd += g_dis[s];
    }
#pragma unroll
    for (int off = 16; off; off >>= 1) {
        m = fmaxf(m, __shfl_xor_sync(0xffffffffu, m, off));
        sd += __shfl_xor_sync(0xffffffffu, sd, off);
    }

    float4 S1 = make_float4(0, 0, 0, 0), Sd = S1, Sa = S1;
    float z = 0.f;
    int i = start;
    for (; i + 1 < end; i += 2) {
        int s0 = g_col[i], s1 = g_col[i + 1];
        float l0 = g_ls[s0] + ldn; l0 = (l0 >= 0.f) ? l0 : 0.2f * l0;
        float l1 = g_ls[s1] + ldn; l1 = (l1 >= 0.f) ? l1 : 0.2f * l1;
        float e0 = __expf(l0 - m), e1 = __expf(l1 - m);
        float d0 = g_dis[s0], d1 = g_dis[s1];
        float4 a0 = *(const float4*)&cur[(size_t)s0 * HH + lane * 4];
        float4 a1 = *(const float4*)&cur[(size_t)s1 * HH + lane * 4];
        z += e0 + e1;
        S1.x += a0.x + a1.x; S1.y += a0.y + a1.y;
        S1.z += a0.z + a1.z; S1.w += a0.w + a1.w;
        Sd.x += d0 * a0.x + d1 * a1.x; Sd.y += d0 * a0.y + d1 * a1.y;
        Sd.z += d0 * a0.z + d1 * a1.z; Sd.w += d0 * a0.w + d1 * a1.w;
        Sa.x += e0 * a0.x + e1 * a1.x; Sa.y += e0 * a0.y + e1 * a1.y;
        Sa.z += e0 * a0.z + e1 * a1.z; Sa.w += e0 * a0.w + e1 * a1.w;
    }
    if (i < end) {
        int s = g_col[i];
        float l = g_ls[s] + ldn;
        l = (l >= 0.f) ? l : 0.2f * l;
        float e = __expf(l - m);
        float ds = g_dis[s];
        float4 x4 = *(const float4*)&cur[(size_t)s * HH + lane * 4];
        z += e;
        S1.x += x4.x; S1.y += x4.y; S1.z += x4.z; S1.w += x4.w;
        Sd.x += ds * x4.x; Sd.y += ds * x4.y; Sd.z += ds * x4.z; Sd.w += ds * x4.w;
        Sa.x += e * x4.x; Sa.y += e * x4.y; Sa.z += e * x4.z; Sa.w += e * x4.w;
    }

    float deg = (float)(end - start);
    float inv = 1.f / fmaxf(deg, 1.f);
    float eps1 = 1.f + *eps_ptr;
    float disn = g_dis[n];
    float zinv = 1.f / (z + 1e-16f);
    float4 c4 = *(const float4*)&cur[(size_t)n * HH + lane * 4];
    size_t o = (size_t)n * HH + lane * 4;

    float4 t;
    t.x = S1.x * inv; t.y = S1.y * inv; t.z = S1.z * inv; t.w = S1.w * inv;
    *(float4*)&g_aggn[o] = t;
    t.x = eps1 * c4.x + S1.x; t.y = eps1 * c4.y + S1.y;
    t.z = eps1 * c4.z + S1.z; t.w = eps1 * c4.w + S1.w;
    *(float4*)&g_ginin[o] = t;
    t.x = disn * Sd.x; t.y = disn * Sd.y; t.z = disn * Sd.z; t.w = disn * Sd.w;
    *(float4*)&g_gcnin[o] = t;
    t.x = zinv * Sa.x; t.y = zinv * Sa.y; t.z = zinv * Sa.z; t.w = zinv * Sa.w;
    *(float4*)&g_gatin[o] = t;
    if (lane == 0) g_sn[n] = disn * sd;
}

// ==================== mma helpers ====================
struct MmaAcc { float a[2][8][4]; };
__device__ __forceinline__ void mma_zero(MmaAcc& A) {
#pragma unroll
    for (int i = 0; i < 2; i++)
#pragma unroll
        for (int j = 0; j < 8; j++)
#pragma unroll
            for (int k = 0; k < 4; k++) A.a[i][j][k] = 0.f;
}

__device__ __forceinline__ void stage_A(const float* __restrict__ A, int row0, int tid,
                                        __nv_bfloat16* sAhi, __nv_bfloat16* sAlo) {
    const float4* Ag = (const float4*)A;
#pragma unroll
    for (int it = 0; it < 16; it++) {
        int idx = tid + it * 256;
        int r = idx >> 5, c4 = idx & 31;
        int gr = row0 + r;
        float4 v = (gr < NN) ? Ag[(size_t)gr * 32 + c4] : make_float4(0, 0, 0, 0);
        __nv_bfloat16 hx = __float2bfloat16(v.x), hy = __float2bfloat16(v.y);
        __nv_bfloat16 hz = __float2bfloat16(v.z), hw = __float2bfloat16(v.w);
        unsigned h0 = pack2bf(hx, hy), h1 = pack2bf(hz, hw);
        unsigned l0 = pack2bf(__float2bfloat16(v.x - __bfloat162float(hx)),
                              __float2bfloat16(v.y - __bfloat162float(hy)));
        unsigned l1 = pack2bf(__float2bfloat16(v.z - __bfloat162float(hz)),
                              __float2bfloat16(v.w - __bfloat162float(hw)));
        *(uint2*)&sAhi[r * 136 + c4 * 4] = make_uint2(h0, h1);
        *(uint2*)&sAlo[r * 136 + c4 * 4] = make_uint2(l0, l1);
    }
}

__device__ __forceinline__ void issue_w_chunk(int tid, uint32_t sWU_,
                                              const __nv_bfloat16* WHp,
                                              const __nv_bfloat16* WLp, int c) {
    int kh = c >> 1;
    const __nv_bfloat16* Wsrc = (c & 1) ? WLp : WHp;
#pragma unroll
    for (int it = 0; it < 4; it++) {
        int idx = tid + it * 256;
        int rrow = idx >> 3, c8 = (idx & 7) * 8;
        uint32_t d = sWU_ + (uint32_t)(rrow * 72 + c8) * 2;
        const void* s = Wsrc + rrow * 128 + kh * 64 + c8;
        asm volatile("cp.async.cg.shared.global [%0], [%1], 16;" :: "r"(d), "l"(s));
    }
    asm volatile("cp.async.commit_group;" ::: "memory");
}

// ==================== GEMM: M=128 tile, cp.async double-buffered W, full chunk unroll ====================
#define SMEM_GEMM 107008
template <int SA1, int WI1, int SA2, int WI2, int DST, int BMODE, int CMODE, int LSLDV, int OP>
__global__ void __launch_bounds__(256, 2)
gemm_mma(const float* __restrict__ A1p, const float* __restrict__ bias, int l) {
    extern __shared__ char smem[];
    __nv_bfloat16* sAhi = (__nv_bfloat16*)smem;
    __nv_bfloat16* sAlo = sAhi + 128 * 136;
    __nv_bfloat16* sW0  = sAlo + 128 * 136;
    __nv_bfloat16* sW1  = sW0 + 128 * 72;
    float* sbias = (float*)(sW1 + 128 * 72);
    const int tid = threadIdx.x, lane = tid & 31, warp = tid >> 5;
    const int wm = warp >> 1, wn = warp & 1;
    const int row0 = blockIdx.x * 128;
    if (BMODE && tid < 128) sbias[tid] = bias[tid];
    const uint32_t sAhiU = smem_u32(sAhi), sAloU = smem_u32(sAlo);
    const uint32_t sW0U = smem_u32(sW0), sW1U = smem_u32(sW1);

    MmaAcc acc;
    mma_zero(acc);

    const int npass = (SA2 >= 0) ? 2 : 1;
#pragma unroll 1
    for (int pass = 0; pass < npass; pass++) {
        const float* A = (pass == 0)
            ? ((SA1 < 0) ? A1p : buf<(SA1 < 0) ? 0 : SA1>())
            : buf<(SA2 < 0) ? 0 : SA2>();
        const int wi = (pass == 0) ? WI1 : ((WI2 < 0) ? 0 : WI2);
        const __nv_bfloat16* WHp = g_wh + wi * 16384;
        const __nv_bfloat16* WLp = g_wl + wi * 16384;

        __syncthreads();
        issue_w_chunk(tid, sW0U, WHp, WLp, 0);
        stage_A(A, row0, tid, sAhi, sAlo);

#pragma unroll
        for (int c = 0; c < 4; c++) {
            asm volatile("cp.async.wait_group 0;" ::: "memory");
            __syncthreads();
            if (c < 3) issue_w_chunk(tid, (c & 1) ? sW0U : sW1U, WHp, WLp, c + 1);
            const uint32_t sWU = (c & 1) ? sW1U : sW0U;
            const int kh = c >> 1, wv = c & 1;
#pragma unroll
            for (int ks = 0; ks < 4; ks++) {
                int k0 = ks * 16;
                uint32_t bfr[4][4];
#pragma unroll
                for (int p = 0; p < 4; p++) {
                    int grp = lane >> 3, rr = lane & 7;
                    int row = wn * 64 + p * 16 + ((grp >> 1) << 3) + rr;
                    int col = k0 + ((grp & 1) << 3);
                    uint32_t ad = sWU + (row * 72 + col) * 2;
                    asm volatile(
                        "ldmatrix.sync.aligned.m8n8.x4.shared.b16 {%0,%1,%2,%3}, [%4];"
                        : "=r"(bfr[p][0]), "=r"(bfr[p][1]), "=r"(bfr[p][2]), "=r"(bfr[p][3])
                        : "r"(ad));
                }
                uint32_t af[2][4];
#pragma unroll
                for (int mi = 0; mi < 2; mi++) {
                    int grp = lane >> 3, rr = lane & 7;
                    int row = wm * 32 + mi * 16 + ((grp & 1) << 3) + rr;
                    int col = kh * 64 + k0 + ((grp >> 1) << 3);
                    uint32_t ad = sAhiU + (row * 136 + col) * 2;
                    asm volatile(
                        "ldmatrix.sync.aligned.m8n8.x4.shared.b16 {%0,%1,%2,%3}, [%4];"
                        : "=r"(af[mi][0]), "=r"(af[mi][1]), "=r"(af[mi][2]), "=r"(af[mi][3])
                        : "r"(ad));
                }
#pragma unroll
                for (int mi = 0; mi < 2; mi++)
#pragma unroll
                    for (int ni = 0; ni < 8; ni++) {
                        uint32_t b0 = bfr[ni >> 1][(ni & 1) * 2];
                        uint32_t b1 = bfr[ni >> 1][(ni & 1) * 2 + 1];
                        asm volatile(
                            "mma.sync.aligned.m16n8k16.row.col.f32.bf16.bf16.f32 "
                            "{%0,%1,%2,%3}, {%4,%5,%6,%7}, {%8,%9}, {%0,%1,%2,%3};"
                            : "+f"(acc.a[mi][ni][0]), "+f"(acc.a[mi][ni][1]),
                              "+f"(acc.a[mi][ni][2]), "+f"(acc.a[mi][ni][3])
                            : "r"(af[mi][0]), "r"(af[mi][1]), "r"(af[mi][2]), "r"(af[mi][3]),
                              "r"(b0), "r"(b1));
                    }
                if (wv == 0) {
                    uint32_t al[2][4];
#pragma unroll
                    for (int mi = 0; mi < 2; mi++) {
                        int grp = lane >> 3, rr = lane & 7;
                        int row = wm * 32 + mi * 16 + ((grp & 1) << 3) + rr;
                        int col = kh * 64 + k0 + ((grp >> 1) << 3);
                        uint32_t ad = sAloU + (row * 136 + col) * 2;
                        asm volatile(
                            "ldmatrix.sync.aligned.m8n8.x4.shared.b16 {%0,%1,%2,%3}, [%4];"
                            : "=r"(al[mi][0]), "=r"(al[mi][1]), "=r"(al[mi][2]), "=r"(al[mi][3])
                            : "r"(ad));
                    }
#pragma unroll
                    for (int mi = 0; mi < 2; mi++)
#pragma unroll
                        for (int ni = 0; ni < 8; ni++) {
                            uint32_t b0 = bfr[ni >> 1][(ni & 1) * 2];
                            uint32_t b1 = bfr[ni >> 1][(ni & 1) * 2 + 1];
                            asm volatile(
                                "mma.sync.aligned.m16n8k16.row.col.f32.bf16.bf16.f32 "
                                "{%0,%1,%2,%3}, {%4,%5,%6,%7}, {%8,%9}, {%0,%1,%2,%3};"
                                : "+f"(acc.a[mi][ni][0]), "+f"(acc.a[mi][ni][1]),
                                  "+f"(acc.a[mi][ni][2]), "+f"(acc.a[mi][ni][3])
                                : "r"(al[mi][0]), "r"(al[mi][1]), "r"(al[mi][2]), "r"(al[mi][3]),
                                  "r"(b0), "r"(b1));
                        }
                }
            }
        }
    }
    __syncthreads();

    // ---------- epilogue ----------
    const float w = (CMODE >= 1) ? g_naw[l * 4 + OP] : 0.f;
    const int lv = (LSLDV >= 0) ? LSLDV : 0;
    const float* vsv = g_vs + lv * HH;
    const float* vdv = g_vd + lv * HH;
    float* C = buf<DST>();
#pragma unroll
    for (int mi = 0; mi < 2; mi++) {
        int rA = row0 + wm * 32 + mi * 16 + (lane >> 2);
        int rB = rA + 8;
        float snA = 0.f, snB = 0.f;
        if (BMODE == 2) {
            snA = (rA < NN) ? g_sn[rA] : 0.f;
            snB = (rB < NN) ? g_sn[rB] : 0.f;
        }
        float psA = 0.f, pdA = 0.f, psB = 0.f, pdB = 0.f;
#pragma unroll
        for (int ni = 0; ni < 8; ni++) {
            int col = wn * 64 + ni * 8 + (lane & 3) * 2;
            float2 vA = make_float2(acc.a[mi][ni][0], acc.a[mi][ni][1]);
            float2 vB = make_float2(acc.a[mi][ni][2], acc.a[mi][ni][3]);
            if (BMODE == 1) {
                vA.x += sbias[col]; vA.y += sbias[col + 1];
                vB.x += sbias[col]; vB.y += sbias[col + 1];
            }
            if (BMODE == 2) {
                vA.x += snA * sbias[col]; vA.y += snA * sbias[col + 1];
                vB.x += snB * sbias[col]; vB.y += snB * sbias[col + 1];
            }
            if (CMODE >= 1) {
                vA.x = w * eluf(vA.x); vA.y = w * eluf(vA.y);
                vB.x = w * eluf(vB.x); vB.y = w * eluf(vB.y);
            }
            if (rA < NN) {
                float2* cp = (float2*)&C[(size_t)rA * HH + col];
                if (CMODE == 2) { float2 o = *cp; vA.x += o.x; vA.y += o.y; }
                *cp = vA;
            }
            if (rB < NN) {
                float2* cp = (float2*)&C[(size_t)rB * HH + col];
                if (CMODE == 2) { float2 o = *cp; vB.x += o.x; vB.y += o.y; }
                *cp = vB;
            }
            if (LSLDV >= 0) {
                float s0 = __ldg(&vsv[col]), s1 = __ldg(&vsv[col + 1]);
                float d0 = __ldg(&vdv[col]), d1 = __ldg(&vdv[col + 1]);
                psA += vA.x * s0 + vA.y * s1; pdA += vA.x * d0 + vA.y * d1;
                psB += vB.x * s0 + vB.y * s1; pdB += vB.x * d0 + vB.y * d1;
            }
        }
        if (LSLDV >= 0) {
            psA += __shfl_xor_sync(0xffffffffu, psA, 1);
            psA += __shfl_xor_sync(0xffffffffu, psA, 2);
            pdA += __shfl_xor_sync(0xffffffffu, pdA, 1);
            pdA += __shfl_xor_sync(0xffffffffu, pdA, 2);
            psB += __shfl_xor_sync(0xffffffffu, psB, 1);
            psB += __shfl_xor_sync(0xffffffffu, psB, 2);
            pdB += __shfl_xor_sync(0xffffffffu, pdB, 1);
            pdB += __shfl_xor_sync(0xffffffffu, pdB, 2);
            if ((lane & 3) == 0) {
                if (rA < NN) { atomicAdd(&g_ls[rA], psA); atomicAdd(&g_ld[rA], pdA); }
                if (rB < NN) { atomicAdd(&g_ls[rB], psB); atomicAdd(&g_ld[rB], pdB); }
            }
        }
    }
}

// ==================== fused x5 + node classifier ====================
__global__ void __launch_bounds__(256)
nc_fused_kernel(const float* __restrict__ Wnc, const float* __restrict__ bnc,
                float* __restrict__ out) {
    __shared__ float Ws[NC * 132];
    __shared__ float bs[NC];
    int tid = threadIdx.x;
    for (int i = tid; i < NC * HH; i += 256) {
        int j = i / HH, k = i % HH;
        Ws[j * 132 + k] = Wnc[i];
    }
    if (tid < NC) bs[tid] = bnc[tid];
    __syncthreads();
    int row = blockIdx.x * 64 + (tid >> 2);
    int c0 = (tid & 3) * 10;
    if (row >= NN) return;
    float sc0 = g_scw[1], sc1 = g_scw[3];
    float la0 = g_law[0], la1 = g_law[1], la2 = g_law[2];
    float acc[10];
#pragma unroll
    for (int j = 0; j < 10; j++) acc[j] = 0.f;
    const float* r3 = &g_x3[(size_t)row * HH];
    const float* r1 = &g_x1[(size_t)row * HH];
    const float* r2 = &g_x2[(size_t)row * HH];
    for (int k = 0; k < HH; k += 4) {
        float4 a = *(const float4*)&r3[k];
        float4 b = *(const float4*)&r1[k];
        float4 c = *(const float4*)&r2[k];
        float x5v[4];
#define ONE(i, f)                                                               \
        {                                                                       \
            float bb = sc0 * b.f, cc = sc1 * c.f;                               \
            float mx = fmaxf(fmaxf(a.f, bb), cc);                               \
            float sm = a.f + bb + cc;                                           \
            float mn = sm * (1.f / 3.f);                                        \
            x5v[i] = la0 * fmaxf(mx, 0.f) + la1 * fmaxf(mn, 0.f) + la2 * fmaxf(sm, 0.f); \
        }
        ONE(0, x) ONE(1, y) ONE(2, z) ONE(3, w)
#undef ONE
#pragma unroll
        for (int j = 0; j < 10; j++) {
            acc[j] += x5v[0] * Ws[(c0 + j) * 132 + k]     + x5v[1] * Ws[(c0 + j) * 132 + k + 1]
                    + x5v[2] * Ws[(c0 + j) * 132 + k + 2] + x5v[3] * Ws[(c0 + j) * 132 + k + 3];
        }
    }
#pragma unroll
    for (int j = 0; j < 10; j++) out[row * NC + c0 + j] = acc[j] + bs[c0 + j];
}

// ==================== host ====================
static const int TPB = 256;
static const int GGB = (NN + 127) / 128;   // 391
static const int SB  = (NN + 255) / 256;   // 196

#define LAUNCH_GEMM(SA1, WI1, SA2, WI2, DST, BM_, CM_, LV_, OP_, Aptr, Bptr, lArg)    \
    do {                                                                              \
        cudaFuncSetAttribute(gemm_mma<SA1, WI1, SA2, WI2, DST, BM_, CM_, LV_, OP_>,   \
                             cudaFuncAttributeMaxDynamicSharedMemorySize, SMEM_GEMM); \
        gemm_mma<SA1, WI1, SA2, WI2, DST, BM_, CM_, LV_, OP_>                         \
            <<<GGB, 256, SMEM_GEMM>>>(Aptr, Bptr, lArg);                              \
    } while (0)

template <int CUR, int DST, int L>
static void run_layer(const float* gcn_b, const float* gin_b, const float* gin_eps) {
    agg2_kernel<CUR><<<(NN * 32 + TPB - 1) / TPB, TPB>>>(gin_eps + L);
    // GCN: first combine write
    LAUNCH_GEMM(4, 1 + L, -1, -1, DST, 2, 1, -1, 0, nullptr, gcn_b + L * HH, L);
    // GAT: RMW
    LAUNCH_GEMM(5, 13 + L, -1, -1, DST, 0, 2, -1, 3, nullptr, nullptr, L);
    // SAGE (dual): RMW
    LAUNCH_GEMM(CUR, 4 + L, 6, 7 + L, DST, 0, 2, -1, 1, nullptr, nullptr, L);
    // GIN: RMW, final -> also produces lsld for next layer
    if (L < 2) zero_lsld_kernel<<<SB, 256>>>();
    constexpr int LV = (L < 2) ? (L + 1) : -1;
    LAUNCH_GEMM(7, 10 + L, -1, -1, DST, 1, 2, LV, 2, nullptr, gin_b + L * HH, L);
}

extern "C" void kernel_launch(void* const* d_in, const int* in_sizes, int n_in,
                              void* d_out, int out_size) {
    const float* x       = (const float*)d_in[0];
    const void*  ei      = d_in[1];
    const float* na_a    = (const float*)d_in[2];
    const float* sc_a    = (const float*)d_in[3];
    const float* la_a    = (const float*)d_in[4];
    const float* lin1_W  = (const float*)d_in[5];
    const float* lin1_b  = (const float*)d_in[6];
    const float* gcn_W   = (const float*)d_in[7];
    const float* gcn_b   = (const float*)d_in[8];
    const float* sage_Ws = (const float*)d_in[9];
    const float* sage_Wn = (const float*)d_in[10];
    const float* gin_W   = (const float*)d_in[11];
    const float* gin_b   = (const float*)d_in[12];
    const float* gin_eps = (const float*)d_in[13];
    const float* gat_W   = (const float*)d_in[14];
    const float* gat_as  = (const float*)d_in[15];
    const float* gat_ad  = (const float*)d_in[16];
    const float* nc_W    = (const float*)d_in[17];
    const float* nc_b    = (const float*)d_in[18];
    float*       out     = (float*)d_out;

    WP wp;
    wp.p[0] = lin1_W;
    for (int l = 0; l < 3; l++) {
        wp.p[1 + l]  = gcn_W + l * HH * HH;
        wp.p[4 + l]  = sage_Ws + l * HH * HH;
        wp.p[7 + l]  = sage_Wn + l * HH * HH;
        wp.p[10 + l] = gin_W + l * HH * HH;
        wp.p[13 + l] = gat_W + l * HH * HH;
    }
    // order: lin1 GEMM is the 4th launch (ncu captures launch #4)
    convert_w_kernel<<<dim3(64, 16), 256>>>(wp);                       // 1
    gatvec_kernel<<<dim3(2, 3), 128>>>(gat_W, gat_as, gat_ad);         // 2
    zero_lsld_kernel<<<SB, 256>>>();                                   // 3
    LAUNCH_GEMM(-1, 0, -1, -1, 0, 1, 0, 0, 0, x, lin1_b, 0);           // 4  <- profiled
    detect_kernel<<<1, 512>>>((const int*)ei);                         // 5
    zero_cnt_kernel<<<SB, 256>>>();                                    // 6
    count_kernel<<<(EE + TPB - 1) / TPB, TPB>>>(ei);                   // 7
    scan_part<<<SB, 256>>>();
    scan_mid<<<1, 256>>>();
    scan_fin<<<SB, 256>>>();
    fill_kernel<<<(EE + TPB - 1) / TPB, TPB>>>(ei);
    degdis_kernel<<<SB, 256>>>();
    softmax_small_kernel<<<1, 32>>>(na_a, sc_a, la_a);

    run_layer<0, 1, 0>(gcn_b, gin_b, gin_eps);
    run_layer<1, 2, 1>(gcn_b, gin_b, gin_eps);
    run_layer<2, 3, 2>(gcn_b, gin_b, gin_eps);

    nc_fused_kernel<<<(NN + 63) / 64, 256>>>(nc_W, nc_b, out);
}

// round 17
// speedup vs baseline: 1.6220x; 1.2365x over previous
#include <cuda_runtime.h>
#include <cuda_bf16.h>
#include <math.h>
#include <stdint.h>

#define NN 50000
#define EE 800000
#define HH 128
#define NC 40

// ==================== scratch ====================
__device__ int   g_is64;
__device__ int   g_cnt[NN];
__device__ int   g_part[256];
__device__ int   g_rowptr[NN + 1];
__device__ int   g_wr[NN];
__device__ int   g_col[EE];
__device__ float g_dis[NN];
__device__ float g_sn[NN];
__device__ float g_ls[NN], g_ld[NN];
__device__ float g_vs[3 * HH], g_vd[3 * HH];
__device__ float g_h0[NN * HH];
__device__ float g_x1[NN * HH], g_x2[NN * HH], g_x3[NN * HH];
__device__ float g_gcnin[NN * HH], g_gatin[NN * HH];
__device__ float g_aggn[NN * HH], g_ginin[NN * HH];
__device__ float g_naw[12], g_scw[4], g_law[3];
__device__ __nv_bfloat16 g_wh[16 * 16384];
__device__ __nv_bfloat16 g_wl[16 * 16384];

template <int ID>
__device__ __forceinline__ float* buf() {
    if (ID == 0)  return g_h0;
    if (ID == 1)  return g_x1;
    if (ID == 2)  return g_x2;
    if (ID == 3)  return g_x3;
    if (ID == 4)  return g_gcnin;
    if (ID == 5)  return g_gatin;
    if (ID == 6)  return g_aggn;
    return g_ginin;
}

__device__ __forceinline__ float eluf(float x) { return x > 0.f ? x : expm1f(x); }
__device__ __forceinline__ int edge_at(const void* p, int idx) {
    if (g_is64) return (int)((const long long*)p)[idx];
    return ((const int*)p)[idx];
}
__device__ __forceinline__ uint32_t smem_u32(const void* p) {
    uint32_t a;
    asm("{ .reg .u64 t; cvta.to.shared.u64 t, %1; cvt.u32.u64 %0, t; }" : "=r"(a) : "l"(p));
    return a;
}
__device__ __forceinline__ unsigned pack2bf(__nv_bfloat16 a, __nv_bfloat16 b) {
    return (unsigned)__bfloat16_as_ushort(a) | ((unsigned)__bfloat16_as_ushort(b) << 16);
}

// ==================== edge dtype detection ====================
__global__ void detect_kernel(const int* __restrict__ p) {
    __shared__ int nz;
    if (threadIdx.x == 0) nz = 0;
    __syncthreads();
    int local = 0;
    for (int i = threadIdx.x * 2 + 1; i < 8192; i += 2 * blockDim.x)
        if (p[i] != 0) local = 1;
    if (local) atomicOr(&nz, 1);
    __syncthreads();
    if (threadIdx.x == 0) g_is64 = nz ? 0 : 1;
}

// ==================== tiny softmaxes ====================
__global__ void softmax_small_kernel(const float* __restrict__ na,
                                     const float* __restrict__ sc,
                                     const float* __restrict__ la) {
    if (threadIdx.x != 0 || blockIdx.x != 0) return;
    for (int r = 0; r < 3; r++) {
        float m = -1e30f;
        for (int j = 0; j < 4; j++) m = fmaxf(m, na[r * 4 + j]);
        float z = 0.f, e[4];
        for (int j = 0; j < 4; j++) { e[j] = expf(na[r * 4 + j] - m); z += e[j]; }
        for (int j = 0; j < 4; j++) g_naw[r * 4 + j] = e[j] / z;
    }
    for (int r = 0; r < 2; r++) {
        float m = fmaxf(sc[r * 2], sc[r * 2 + 1]);
        float e0 = expf(sc[r * 2] - m), e1 = expf(sc[r * 2 + 1] - m);
        g_scw[r * 2] = e0 / (e0 + e1);
        g_scw[r * 2 + 1] = e1 / (e0 + e1);
    }
    {
        float m = fmaxf(fmaxf(la[0], la[1]), la[2]);
        float e0 = expf(la[0] - m), e1 = expf(la[1] - m), e2 = expf(la[2] - m);
        float z = e0 + e1 + e2;
        g_law[0] = e0 / z; g_law[1] = e1 / z; g_law[2] = e2 / z;
    }
}

// ==================== CSR build ====================
__global__ void zero_cnt_kernel() {
    int i = blockIdx.x * blockDim.x + threadIdx.x;
    if (i < NN) g_cnt[i] = 0;
}
__global__ void count_kernel(const void* __restrict__ ei) {
    int e = blockIdx.x * blockDim.x + threadIdx.x;
    if (e >= EE) return;
    int dst = edge_at(ei, EE + e);
    if ((unsigned)dst >= NN) return;
    atomicAdd(&g_cnt[dst], 1);
}
__global__ void scan_part() {
    int tid = threadIdx.x, lane = tid & 31, wid = tid >> 5;
    int idx = blockIdx.x * 256 + tid;
    int v = (idx < NN) ? g_cnt[idx] : 0;
#pragma unroll
    for (int off = 16; off; off >>= 1) v += __shfl_xor_sync(0xffffffffu, v, off);
    __shared__ int ws[8];
    if (lane == 0) ws[wid] = v;
    __syncthreads();
    if (tid == 0) {
        int s = 0;
#pragma unroll
        for (int i = 0; i < 8; i++) s += ws[i];
        g_part[blockIdx.x] = s;
    }
}
__global__ void scan_mid() {
    int tid = threadIdx.x, lane = tid & 31, wid = tid >> 5;
    int v = (tid < 196) ? g_part[tid] : 0;
    int incl = v;
#pragma unroll
    for (int off = 1; off < 32; off <<= 1) {
        int t = __shfl_up_sync(0xffffffffu, incl, off);
        if (lane >= off) incl += t;
    }
    __shared__ int ws[8];
    __shared__ int tot;
    if (lane == 31) ws[wid] = incl;
    __syncthreads();
    if (wid == 0) {
        int u = (lane < 8) ? ws[lane] : 0, ui = u;
#pragma unroll
        for (int off = 1; off < 8; off <<= 1) {
            int t = __shfl_up_sync(0xffffffffu, ui, off);
            if (lane >= off) ui += t;
        }
        if (lane < 8) ws[lane] = ui - u;
        if (lane == 7) tot = ui;
    }
    __syncthreads();
    int excl = ws[wid] + incl - v;
    if (tid < 196) g_part[tid] = excl;
    if (tid == 0) g_rowptr[NN] = tot;
}
__global__ void scan_fin() {
    int tid = threadIdx.x, lane = tid & 31, wid = tid >> 5;
    int idx = blockIdx.x * 256 + tid;
    int v = (idx < NN) ? g_cnt[idx] : 0;
    int incl = v;
#pragma unroll
    for (int off = 1; off < 32; off <<= 1) {
        int t = __shfl_up_sync(0xffffffffu, incl, off);
        if (lane >= off) incl += t;
    }
    __shared__ int ws[8];
    if (lane == 31) ws[wid] = incl;
    __syncthreads();
    if (wid == 0) {
        int u = (lane < 8) ? ws[lane] : 0, ui = u;
#pragma unroll
        for (int off = 1; off < 8; off <<= 1) {
            int t = __shfl_up_sync(0xffffffffu, ui, off);
            if (lane >= off) ui += t;
        }
        if (lane < 8) ws[lane] = ui - u;
    }
    __syncthreads();
    int excl = g_part[blockIdx.x] + ws[wid] + incl - v;
    if (idx < NN) { g_rowptr[idx] = excl; g_wr[idx] = excl; }
}
__global__ void fill_kernel(const void* __restrict__ ei) {
    int e = blockIdx.x * blockDim.x + threadIdx.x;
    if (e >= EE) return;
    int src = edge_at(ei, e);
    int dst = edge_at(ei, EE + e);
    if ((unsigned)dst >= NN || (unsigned)src >= NN) return;
    int pos = atomicAdd(&g_wr[dst], 1);
    if ((unsigned)pos < EE) g_col[pos] = src;
}
__global__ void degdis_kernel() {
    int i = blockIdx.x * blockDim.x + threadIdx.x;
    if (i >= NN) return;
    int c = g_cnt[i];
    g_dis[i] = (c > 0) ? rsqrtf((float)c) : 0.f;
}
__global__ void zero_lsld_kernel() {
    int i = blockIdx.x * blockDim.x + threadIdx.x;
    if (i < NN) { g_ls[i] = 0.f; g_ld[i] = 0.f; }
}
// zero next-layer buffer (+ lsld when ZL)
template <int DST, bool ZL>
__global__ void zero_nxt_kernel() {
    int i = blockIdx.x * blockDim.x + threadIdx.x;
    float* C = buf<DST>();
    if (i < NN * HH / 4) ((float4*)C)[i] = make_float4(0.f, 0.f, 0.f, 0.f);
    if (ZL && i < NN) { g_ls[i] = 0.f; g_ld[i] = 0.f; }
}

// ==================== weight conversion ====================
struct WP { const float* p[16]; };
__global__ void convert_w_kernel(WP wp) {
    int mat = blockIdx.y;
    int i = blockIdx.x * 256 + threadIdx.x;
    float v = wp.p[mat][i];
    __nv_bfloat16 h = __float2bfloat16(v);
    __nv_bfloat16 l = __float2bfloat16(v - __bfloat162float(h));
    g_wh[mat * 16384 + i] = h;
    g_wl[mat * 16384 + i] = l;
}

// ==================== GAT projection vectors ====================
__global__ void gatvec_kernel(const float* __restrict__ gat_W,
                              const float* __restrict__ gat_as,
                              const float* __restrict__ gat_ad) {
    int l = blockIdx.y, which = blockIdx.x, k = threadIdx.x;
    const float* W = gat_W + l * HH * HH;
    const float* a = (which ? gat_ad : gat_as) + l * HH;
    float acc = 0.f;
    for (int n = 0; n < HH; n++) acc += W[n * HH + k] * a[n];
    (which ? g_vd : g_vs)[l * HH + k] = acc;
}

// ==================== edge aggregation (2-way unrolled gather, MUFU exp) ====================
template <int CUR>
__global__ void __launch_bounds__(256) agg2_kernel(const float* __restrict__ eps_ptr) {
    const float* cur = buf<CUR>();
    int n = (blockIdx.x * blockDim.x + threadIdx.x) >> 5;
    int lane = threadIdx.x & 31;
    if (n >= NN) return;
    int start = g_rowptr[n], end = g_rowptr[n + 1];
    float ldn = g_ld[n];

    float m = -INFINITY, sd = 0.f;
    for (int i = start + lane; i < end; i += 32) {
        int s = g_col[i];
        float l = g_ls[s] + ldn;
        l = (l >= 0.f) ? l : 0.2f * l;
        m = fmaxf(m, l);
        sd += g_dis[s];
    }
#pragma unroll
    for (int off = 16; off; off >>= 1) {
        m = fmaxf(m, __shfl_xor_sync(0xffffffffu, m, off));
        sd += __shfl_xor_sync(0xffffffffu, sd, off);
    }

    float4 S1 = make_float4(0, 0, 0, 0), Sd = S1, Sa = S1;
    float z = 0.f;
    int i = start;
    for (; i + 1 < end; i += 2) {
        int s0 = g_col[i], s1 = g_col[i + 1];
        float l0 = g_ls[s0] + ldn; l0 = (l0 >= 0.f) ? l0 : 0.2f * l0;
        float l1 = g_ls[s1] + ldn; l1 = (l1 >= 0.f) ? l1 : 0.2f * l1;
        float e0 = __expf(l0 - m), e1 = __expf(l1 - m);
        float d0 = g_dis[s0], d1 = g_dis[s1];
        float4 a0 = *(const float4*)&cur[(size_t)s0 * HH + lane * 4];
        float4 a1 = *(const float4*)&cur[(size_t)s1 * HH + lane * 4];
        z += e0 + e1;
        S1.x += a0.x + a1.x; S1.y += a0.y + a1.y;
        S1.z += a0.z + a1.z; S1.w += a0.w + a1.w;
        Sd.x += d0 * a0.x + d1 * a1.x; Sd.y += d0 * a0.y + d1 * a1.y;
        Sd.z += d0 * a0.z + d1 * a1.z; Sd.w += d0 * a0.w + d1 * a1.w;
        Sa.x += e0 * a0.x + e1 * a1.x; Sa.y += e0 * a0.y + e1 * a1.y;
        Sa.z += e0 * a0.z + e1 * a1.z; Sa.w += e0 * a0.w + e1 * a1.w;
    }
    if (i < end) {
        int s = g_col[i];
        float l = g_ls[s] + ldn;
        l = (l >= 0.f) ? l : 0.2f * l;
        float e = __expf(l - m);
        float ds = g_dis[s];
        float4 x4 = *(const float4*)&cur[(size_t)s * HH + lane * 4];
        z += e;
        S1.x += x4.x; S1.y += x4.y; S1.z += x4.z; S1.w += x4.w;
        Sd.x += ds * x4.x; Sd.y += ds * x4.y; Sd.z += ds * x4.z; Sd.w += ds * x4.w;
        Sa.x += e * x4.x; Sa.y += e * x4.y; Sa.z += e * x4.z; Sa.w += e * x4.w;
    }

    float deg = (float)(end - start);
    float inv = 1.f / fmaxf(deg, 1.f);
    float eps1 = 1.f + *eps_ptr;
    float disn = g_dis[n];
    float zinv = 1.f / (z + 1e-16f);
    float4 c4 = *(const float4*)&cur[(size_t)n * HH + lane * 4];
    size_t o = (size_t)n * HH + lane * 4;

    float4 t;
    t.x = S1.x * inv; t.y = S1.y * inv; t.z = S1.z * inv; t.w = S1.w * inv;
    *(float4*)&g_aggn[o] = t;
    t.x = eps1 * c4.x + S1.x; t.y = eps1 * c4.y + S1.y;
    t.z = eps1 * c4.z + S1.z; t.w = eps1 * c4.w + S1.w;
    *(float4*)&g_ginin[o] = t;
    t.x = disn * Sd.x; t.y = disn * Sd.y; t.z = disn * Sd.z; t.w = disn * Sd.w;
    *(float4*)&g_gcnin[o] = t;
    t.x = zinv * Sa.x; t.y = zinv * Sa.y; t.z = zinv * Sa.z; t.w = zinv * Sa.w;
    *(float4*)&g_gatin[o] = t;
    if (lane == 0) g_sn[n] = disn * sd;
}

// ==================== mma helpers ====================
struct MmaAcc { float a[2][8][4]; };
__device__ __forceinline__ void mma_zero(MmaAcc& A) {
#pragma unroll
    for (int i = 0; i < 2; i++)
#pragma unroll
        for (int j = 0; j < 8; j++)
#pragma unroll
            for (int k = 0; k < 4; k++) A.a[i][j][k] = 0.f;
}

__device__ __forceinline__ void stage_A(const float* __restrict__ A, int row0, int tid,
                                        __nv_bfloat16* sAhi, __nv_bfloat16* sAlo) {
    const float4* Ag = (const float4*)A;
#pragma unroll
    for (int it = 0; it < 16; it++) {
        int idx = tid + it * 256;
        int r = idx >> 5, c4 = idx & 31;
        int gr = row0 + r;
        float4 v = (gr < NN) ? Ag[(size_t)gr * 32 + c4] : make_float4(0, 0, 0, 0);
        __nv_bfloat16 hx = __float2bfloat16(v.x), hy = __float2bfloat16(v.y);
        __nv_bfloat16 hz = __float2bfloat16(v.z), hw = __float2bfloat16(v.w);
        unsigned h0 = pack2bf(hx, hy), h1 = pack2bf(hz, hw);
        unsigned l0 = pack2bf(__float2bfloat16(v.x - __bfloat162float(hx)),
                              __float2bfloat16(v.y - __bfloat162float(hy)));
        unsigned l1 = pack2bf(__float2bfloat16(v.z - __bfloat162float(hz)),
                              __float2bfloat16(v.w - __bfloat162float(hw)));
        *(uint2*)&sAhi[r * 136 + c4 * 4] = make_uint2(h0, h1);
        *(uint2*)&sAlo[r * 136 + c4 * 4] = make_uint2(l0, l1);
    }
}

__device__ __forceinline__ void issue_w_chunk(int tid, uint32_t sWU_,
                                              const __nv_bfloat16* WHp,
                                              const __nv_bfloat16* WLp, int c) {
    int kh = c >> 1;
    const __nv_bfloat16* Wsrc = (c & 1) ? WLp : WHp;
#pragma unroll
    for (int it = 0; it < 4; it++) {
        int idx = tid + it * 256;
        int rrow = idx >> 3, c8 = (idx & 7) * 8;
        uint32_t d = sWU_ + (uint32_t)(rrow * 72 + c8) * 2;
        const void* s = Wsrc + rrow * 128 + kh * 64 + c8;
        asm volatile("cp.async.cg.shared.global [%0], [%1], 16;" :: "r"(d), "l"(s));
    }
    asm volatile("cp.async.commit_group;" ::: "memory");
}

// core K=128 3-term loop over one A (already staged) and one W (by index)
__device__ __forceinline__ void mma_pass(MmaAcc& acc, int tid, int lane, int wm, int wn,
                                         uint32_t sAhiU, uint32_t sAloU,
                                         uint32_t sW0U, uint32_t sW1U,
                                         const __nv_bfloat16* WHp, const __nv_bfloat16* WLp) {
#pragma unroll
    for (int c = 0; c < 4; c++) {
        asm volatile("cp.async.wait_group 0;" ::: "memory");
        __syncthreads();
        if (c < 3) issue_w_chunk(tid, (c & 1) ? sW0U : sW1U, WHp, WLp, c + 1);
        const uint32_t sWU = (c & 1) ? sW1U : sW0U;
        const int kh = c >> 1, wv = c & 1;
#pragma unroll
        for (int ks = 0; ks < 4; ks++) {
            int k0 = ks * 16;
            uint32_t bfr[4][4];
#pragma unroll
            for (int p = 0; p < 4; p++) {
                int grp = lane >> 3, rr = lane & 7;
                int row = wn * 64 + p * 16 + ((grp >> 1) << 3) + rr;
                int col = k0 + ((grp & 1) << 3);
                uint32_t ad = sWU + (row * 72 + col) * 2;
                asm volatile("ldmatrix.sync.aligned.m8n8.x4.shared.b16 {%0,%1,%2,%3}, [%4];"
                             : "=r"(bfr[p][0]), "=r"(bfr[p][1]), "=r"(bfr[p][2]), "=r"(bfr[p][3])
                             : "r"(ad));
            }
            uint32_t af[2][4];
#pragma unroll
            for (int mi = 0; mi < 2; mi++) {
                int grp = lane >> 3, rr = lane & 7;
                int row = wm * 32 + mi * 16 + ((grp & 1) << 3) + rr;
                int col = kh * 64 + k0 + ((grp >> 1) << 3);
                uint32_t ad = sAhiU + (row * 136 + col) * 2;
                asm volatile("ldmatrix.sync.aligned.m8n8.x4.shared.b16 {%0,%1,%2,%3}, [%4];"
                             : "=r"(af[mi][0]), "=r"(af[mi][1]), "=r"(af[mi][2]), "=r"(af[mi][3])
                             : "r"(ad));
            }
#pragma unroll
            for (int mi = 0; mi < 2; mi++)
#pragma unroll
                for (int ni = 0; ni < 8; ni++) {
                    uint32_t b0 = bfr[ni >> 1][(ni & 1) * 2];
                    uint32_t b1 = bfr[ni >> 1][(ni & 1) * 2 + 1];
                    asm volatile(
                        "mma.sync.aligned.m16n8k16.row.col.f32.bf16.bf16.f32 "
                        "{%0,%1,%2,%3}, {%4,%5,%6,%7}, {%8,%9}, {%0,%1,%2,%3};"
                        : "+f"(acc.a[mi][ni][0]), "+f"(acc.a[mi][ni][1]),
                          "+f"(acc.a[mi][ni][2]), "+f"(acc.a[mi][ni][3])
                        : "r"(af[mi][0]), "r"(af[mi][1]), "r"(af[mi][2]), "r"(af[mi][3]),
                          "r"(b0), "r"(b1));
                }
            if (wv == 0) {
                uint32_t al[2][4];
#pragma unroll
                for (int mi = 0; mi < 2; mi++) {
                    int grp = lane >> 3, rr = lane & 7;
                    int row = wm * 32 + mi * 16 + ((grp & 1) << 3) + rr;
                    int col = kh * 64 + k0 + ((grp >> 1) << 3);
                    uint32_t ad = sAloU + (row * 136 + col) * 2;
                    asm volatile("ldmatrix.sync.aligned.m8n8.x4.shared.b16 {%0,%1,%2,%3}, [%4];"
                                 : "=r"(al[mi][0]), "=r"(al[mi][1]), "=r"(al[mi][2]), "=r"(al[mi][3])
                                 : "r"(ad));
                }
#pragma unroll
                for (int mi = 0; mi < 2; mi++)
#pragma unroll
                    for (int ni = 0; ni < 8; ni++) {
                        uint32_t b0 = bfr[ni >> 1][(ni & 1) * 2];
                        uint32_t b1 = bfr[ni >> 1][(ni & 1) * 2 + 1];
                        asm volatile(
                            "mma.sync.aligned.m16n8k16.row.col.f32.bf16.bf16.f32 "
                            "{%0,%1,%2,%3}, {%4,%5,%6,%7}, {%8,%9}, {%0,%1,%2,%3};"
                            : "+f"(acc.a[mi][ni][0]), "+f"(acc.a[mi][ni][1]),
                              "+f"(acc.a[mi][ni][2]), "+f"(acc.a[mi][ni][3])
                            : "r"(al[mi][0]), "r"(al[mi][1]), "r"(al[mi][2]), "r"(al[mi][3]),
                              "r"(b0), "r"(b1));
                    }
            }
        }
    }
}

// ==================== lin1 GEMM (separate; plain write + lsld atomics) ====================
#define SMEM_GEMM 107008
__global__ void __launch_bounds__(256, 2)
gemm_lin1(const float* __restrict__ A1p, const float* __restrict__ bias) {
    extern __shared__ char smem[];
    __nv_bfloat16* sAhi = (__nv_bfloat16*)smem;
    __nv_bfloat16* sAlo = sAhi + 128 * 136;
    __nv_bfloat16* sW0  = sAlo + 128 * 136;
    __nv_bfloat16* sW1  = sW0 + 128 * 72;
    float* sbias = (float*)(sW1 + 128 * 72);
    const int tid = threadIdx.x, lane = tid & 31, warp = tid >> 5;
    const int wm = warp >> 1, wn = warp & 1;
    const int row0 = blockIdx.x * 128;
    if (tid < 128) sbias[tid] = bias[tid];
    const uint32_t sAhiU = smem_u32(sAhi), sAloU = smem_u32(sAlo);
    const uint32_t sW0U = smem_u32(sW0), sW1U = smem_u32(sW1);

    MmaAcc acc;
    mma_zero(acc);
    __syncthreads();
    issue_w_chunk(tid, sW0U, g_wh, g_wl, 0);
    stage_A(A1p, row0, tid, sAhi, sAlo);
    mma_pass(acc, tid, lane, wm, wn, sAhiU, sAloU, sW0U, sW1U, g_wh, g_wl);
    __syncthreads();

    float* C = g_h0;
#pragma unroll
    for (int mi = 0; mi < 2; mi++) {
        int rA = row0 + wm * 32 + mi * 16 + (lane >> 2);
        int rB = rA + 8;
        float psA = 0.f, pdA = 0.f, psB = 0.f, pdB = 0.f;
#pragma unroll
        for (int ni = 0; ni < 8; ni++) {
            int col = wn * 64 + ni * 8 + (lane & 3) * 2;
            float2 vA = make_float2(acc.a[mi][ni][0] + sbias[col], acc.a[mi][ni][1] + sbias[col + 1]);
            float2 vB = make_float2(acc.a[mi][ni][2] + sbias[col], acc.a[mi][ni][3] + sbias[col + 1]);
            if (rA < NN) *(float2*)&C[(size_t)rA * HH + col] = vA;
            if (rB < NN) *(float2*)&C[(size_t)rB * HH + col] = vB;
            float s0 = __ldg(&g_vs[col]), s1 = __ldg(&g_vs[col + 1]);
            float d0 = __ldg(&g_vd[col]), d1 = __ldg(&g_vd[col + 1]);
            psA += vA.x * s0 + vA.y * s1; pdA += vA.x * d0 + vA.y * d1;
            psB += vB.x * s0 + vB.y * s1; pdB += vB.x * d0 + vB.y * d1;
        }
        psA += __shfl_xor_sync(0xffffffffu, psA, 1);
        psA += __shfl_xor_sync(0xffffffffu, psA, 2);
        pdA += __shfl_xor_sync(0xffffffffu, pdA, 1);
        pdA += __shfl_xor_sync(0xffffffffu, pdA, 2);
        psB += __shfl_xor_sync(0xffffffffu, psB, 1);
        psB += __shfl_xor_sync(0xffffffffu, psB, 2);
        pdB += __shfl_xor_sync(0xffffffffu, pdB, 1);
        pdB += __shfl_xor_sync(0xffffffffu, pdB, 2);
        if ((lane & 3) == 0) {
            if (rA < NN) { atomicAdd(&g_ls[rA], psA); atomicAdd(&g_ld[rA], pdA); }
            if (rB < NN) { atomicAdd(&g_ls[rB], psB); atomicAdd(&g_ld[rB], pdB); }
        }
    }
}

// ==================== batched per-layer GEMM (blockIdx.y = op), atomic combine ====================
#define SMEM_L4 107520
template <int CUR, int DST, int L>
__global__ void __launch_bounds__(256, 2)
gemm_layer4(const float* __restrict__ gcn_b, const float* __restrict__ gin_b) {
    extern __shared__ char smem[];
    __nv_bfloat16* sAhi = (__nv_bfloat16*)smem;
    __nv_bfloat16* sAlo = sAhi + 128 * 136;
    __nv_bfloat16* sW0  = sAlo + 128 * 136;
    __nv_bfloat16* sW1  = sW0 + 128 * 72;
    float* sbg = (float*)(sW1 + 128 * 72);   // 128
    float* sbi = sbg + 128;                  // 128
    const int tid = threadIdx.x, lane = tid & 31, warp = tid >> 5;
    const int wm = warp >> 1, wn = warp & 1;
    const int row0 = blockIdx.x * 128;
    const int op = blockIdx.y;   // 0=GCN 1=GAT 2=SAGE 3=GIN
    if (tid < 128) { sbg[tid] = gcn_b[tid]; sbi[tid] = gin_b[tid]; }
    const uint32_t sAhiU = smem_u32(sAhi), sAloU = smem_u32(sAlo);
    const uint32_t sW0U = smem_u32(sW0), sW1U = smem_u32(sW1);

    const float* A1p; int wi1; const float* A2p = nullptr; int wi2 = 0;
    if (op == 0)      { A1p = g_gcnin;   wi1 = 1 + L; }
    else if (op == 1) { A1p = g_gatin;   wi1 = 13 + L; }
    else if (op == 2) { A1p = buf<CUR>(); wi1 = 4 + L; A2p = g_aggn; wi2 = 7 + L; }
    else              { A1p = g_ginin;   wi1 = 10 + L; }
    const int npass = (op == 2) ? 2 : 1;

    MmaAcc acc;
    mma_zero(acc);
#pragma unroll 1
    for (int pass = 0; pass < npass; pass++) {
        const float* A = (pass == 0) ? A1p : A2p;
        const int wi = (pass == 0) ? wi1 : wi2;
        const __nv_bfloat16* WHp = g_wh + wi * 16384;
        const __nv_bfloat16* WLp = g_wl + wi * 16384;
        __syncthreads();
        issue_w_chunk(tid, sW0U, WHp, WLp, 0);
        stage_A(A, row0, tid, sAhi, sAlo);
        mma_pass(acc, tid, lane, wm, wn, sAhiU, sAloU, sW0U, sW1U, WHp, WLp);
    }
    __syncthreads();

    // ---------- epilogue: atomic combine + partial lsld ----------
    const int opidx = (op == 0) ? 0 : (op == 1) ? 3 : (op == 2) ? 1 : 2;
    const float w = g_naw[L * 4 + opidx];
    const int lv = (L < 2) ? (L + 1) : 0;
    const float* vsv = g_vs + lv * HH;
    const float* vdv = g_vd + lv * HH;
    float* C = buf<DST>();
#pragma unroll
    for (int mi = 0; mi < 2; mi++) {
        int rA = row0 + wm * 32 + mi * 16 + (lane >> 2);
        int rB = rA + 8;
        float snA = 0.f, snB = 0.f;
        if (op == 0) {
            snA = (rA < NN) ? g_sn[rA] : 0.f;
            snB = (rB < NN) ? g_sn[rB] : 0.f;
        }
        float psA = 0.f, pdA = 0.f, psB = 0.f, pdB = 0.f;
#pragma unroll
        for (int ni = 0; ni < 8; ni++) {
            int col = wn * 64 + ni * 8 + (lane & 3) * 2;
            float2 vA = make_float2(acc.a[mi][ni][0], acc.a[mi][ni][1]);
            float2 vB = make_float2(acc.a[mi][ni][2], acc.a[mi][ni][3]);
            if (op == 0) {
                vA.x += snA * sbg[col]; vA.y += snA * sbg[col + 1];
                vB.x += snB * sbg[col]; vB.y += snB * sbg[col + 1];
            }
            if (op == 3) {
                vA.x += sbi[col]; vA.y += sbi[col + 1];
                vB.x += sbi[col]; vB.y += sbi[col + 1];
            }
            vA.x = w * eluf(vA.x); vA.y = w * eluf(vA.y);
            vB.x = w * eluf(vB.x); vB.y = w * eluf(vB.y);
            if (rA < NN) {
                atomicAdd(&C[(size_t)rA * HH + col], vA.x);
                atomicAdd(&C[(size_t)rA * HH + col + 1], vA.y);
            }
            if (rB < NN) {
                atomicAdd(&C[(size_t)rB * HH + col], vB.x);
                atomicAdd(&C[(size_t)rB * HH + col + 1], vB.y);
            }
            if (L < 2) {
                float s0 = __ldg(&vsv[col]), s1 = __ldg(&vsv[col + 1]);
                float d0 = __ldg(&vdv[col]), d1 = __ldg(&vdv[col + 1]);
                psA += vA.x * s0 + vA.y * s1; pdA += vA.x * d0 + vA.y * d1;
                psB += vB.x * s0 + vB.y * s1; pdB += vB.x * d0 + vB.y * d1;
            }
        }
        if (L < 2) {
            psA += __shfl_xor_sync(0xffffffffu, psA, 1);
            psA += __shfl_xor_sync(0xffffffffu, psA, 2);
            pdA += __shfl_xor_sync(0xffffffffu, pdA, 1);
            pdA += __shfl_xor_sync(0xffffffffu, pdA, 2);
            psB += __shfl_xor_sync(0xffffffffu, psB, 1);
            psB += __shfl_xor_sync(0xffffffffu, psB, 2);
            pdB += __shfl_xor_sync(0xffffffffu, pdB, 1);
            pdB += __shfl_xor_sync(0xffffffffu, pdB, 2);
            if ((lane & 3) == 0) {
                if (rA < NN) { atomicAdd(&g_ls[rA], psA); atomicAdd(&g_ld[rA], pdA); }
                if (rB < NN) { atomicAdd(&g_ls[rB], psB); atomicAdd(&g_ld[rB], pdB); }
            }
        }
    }
}

// ==================== fused x5 + node classifier ====================
__global__ void __launch_bounds__(256)
nc_fused_kernel(const float* __restrict__ Wnc, const float* __restrict__ bnc,
                float* __restrict__ out) {
    __shared__ float Ws[NC * 132];
    __shared__ float bs[NC];
    int tid = threadIdx.x;
    for (int i = tid; i < NC * HH; i += 256) {
        int j = i / HH, k = i % HH;
        Ws[j * 132 + k] = Wnc[i];
    }
    if (tid < NC) bs[tid] = bnc[tid];
    __syncthreads();
    int row = blockIdx.x * 64 + (tid >> 2);
    int c0 = (tid & 3) * 10;
    if (row >= NN) return;
    float sc0 = g_scw[1], sc1 = g_scw[3];
    float la0 = g_law[0], la1 = g_law[1], la2 = g_law[2];
    float acc[10];
#pragma unroll
    for (int j = 0; j < 10; j++) acc[j] = 0.f;
    const float* r3 = &g_x3[(size_t)row * HH];
    const float* r1 = &g_x1[(size_t)row * HH];
    const float* r2 = &g_x2[(size_t)row * HH];
    for (int k = 0; k < HH; k += 4) {
        float4 a = *(const float4*)&r3[k];
        float4 b = *(const float4*)&r1[k];
        float4 c = *(const float4*)&r2[k];
        float x5v[4];
#define ONE(i, f)                                                               \
        {                                                                       \
            float bb = sc0 * b.f, cc = sc1 * c.f;                               \
            float mx = fmaxf(fmaxf(a.f, bb), cc);                               \
            float sm = a.f + bb + cc;                                           \
            float mn = sm * (1.f / 3.f);                                        \
            x5v[i] = la0 * fmaxf(mx, 0.f) + la1 * fmaxf(mn, 0.f) + la2 * fmaxf(sm, 0.f); \
        }
        ONE(0, x) ONE(1, y) ONE(2, z) ONE(3, w)
#undef ONE
#pragma unroll
        for (int j = 0; j < 10; j++) {
            acc[j] += x5v[0] * Ws[(c0 + j) * 132 + k]     + x5v[1] * Ws[(c0 + j) * 132 + k + 1]
                    + x5v[2] * Ws[(c0 + j) * 132 + k + 2] + x5v[3] * Ws[(c0 + j) * 132 + k + 3];
        }
    }
#pragma unroll
    for (int j = 0; j < 10; j++) out[row * NC + c0 + j] = acc[j] + bs[c0 + j];
}

// ==================== host ====================
static const int TPB = 256;
static const int GGB = (NN + 127) / 128;   // 391
static const int SB  = (NN + 255) / 256;   // 196

template <int CUR, int DST, int L>
static void run_layer(const float* gcn_b, const float* gin_b, const float* gin_eps) {
    agg2_kernel<CUR><<<(NN * 32 + TPB - 1) / TPB, TPB>>>(gin_eps + L);
    zero_nxt_kernel<DST, (L < 2)><<<(NN * HH / 4 + TPB - 1) / TPB, TPB>>>();
    cudaFuncSetAttribute(gemm_layer4<CUR, DST, L>,
                         cudaFuncAttributeMaxDynamicSharedMemorySize, SMEM_L4);
    gemm_layer4<CUR, DST, L><<<dim3(GGB, 4), 256, SMEM_L4>>>(gcn_b + L * HH, gin_b + L * HH);
}

extern "C" void kernel_launch(void* const* d_in, const int* in_sizes, int n_in,
                              void* d_out, int out_size) {
    const float* x       = (const float*)d_in[0];
    const void*  ei      = d_in[1];
    const float* na_a    = (const float*)d_in[2];
    const float* sc_a    = (const float*)d_in[3];
    const float* la_a    = (const float*)d_in[4];
    const float* lin1_W  = (const float*)d_in[5];
    const float* lin1_b  = (const float*)d_in[6];
    const float* gcn_W   = (const float*)d_in[7];
    const float* gcn_b   = (const float*)d_in[8];
    const float* sage_Ws = (const float*)d_in[9];
    const float* sage_Wn = (const float*)d_in[10];
    const float* gin_W   = (const float*)d_in[11];
    const float* gin_b   = (const float*)d_in[12];
    const float* gin_eps = (const float*)d_in[13];
    const float* gat_W   = (const float*)d_in[14];
    const float* gat_as  = (const float*)d_in[15];
    const float* gat_ad  = (const float*)d_in[16];
    const float* nc_W    = (const float*)d_in[17];
    const float* nc_b    = (const float*)d_in[18];
    float*       out     = (float*)d_out;

    WP wp;
    wp.p[0] = lin1_W;
    for (int l = 0; l < 3; l++) {
        wp.p[1 + l]  = gcn_W + l * HH * HH;
        wp.p[4 + l]  = sage_Ws + l * HH * HH;
        wp.p[7 + l]  = sage_Wn + l * HH * HH;
        wp.p[10 + l] = gin_W + l * HH * HH;
        wp.p[13 + l] = gat_W + l * HH * HH;
    }
    // order: lin1 GEMM is the 4th launch (ncu captures launch #4)
    convert_w_kernel<<<dim3(64, 16), 256>>>(wp);                       // 1
    gatvec_kernel<<<dim3(2, 3), 128>>>(gat_W, gat_as, gat_ad);         // 2
    zero_lsld_kernel<<<SB, 256>>>();                                   // 3
    cudaFuncSetAttribute(gemm_lin1, cudaFuncAttributeMaxDynamicSharedMemorySize, SMEM_GEMM);
    gemm_lin1<<<GGB, 256, SMEM_GEMM>>>(x, lin1_b);                     // 4  <- profiled
    detect_kernel<<<1, 512>>>((const int*)ei);                         // 5
    zero_cnt_kernel<<<SB, 256>>>();                                    // 6
    count_kernel<<<(EE + TPB - 1) / TPB, TPB>>>(ei);                   // 7
    scan_part<<<SB, 256>>>();
    scan_mid<<<1, 256>>>();
    scan_fin<<<SB, 256>>>();
    fill_kernel<<<(EE + TPB - 1) / TPB, TPB>>>(ei);
    degdis_kernel<<<SB, 256>>>();
    softmax_small_kernel<<<1, 32>>>(na_a, sc_a, la_a);

    run_layer<0, 1, 0>(gcn_b, gin_b, gin_eps);
    run_layer<1, 2, 1>(gcn_b, gin_b, gin_eps);
    run_layer<2, 3, 2>(gcn_b, gin_b, gin_eps);

    nc_fused_kernel<<<(NN + 63) / 64, 256>>>(nc_W, nc_b, out);
}